// round 10
// baseline (speedup 1.0000x reference)
#include <cuda_runtime.h>
#include <cstdint>
#include <cstddef>

// ---------------------------------------------------------------------------
// Rel_Transformer_Layer: N=2048, D=1024, H=8, DK=128, L=4, FF=4096
// Round 10: weight GEMMs move to 64x64 warp tiles (CTA 128x256) to cut
// LDS bytes/MMA 192->128 (smem-port-bound per round-9 measurement).
// Flash attention unchanged (round-8 verified).
// ---------------------------------------------------------------------------

#define NTOK 2048
#define DMOD 1024
#define HEADS 8
#define DKH 128
#define FFD 4096
#define SCALE 0.08838834764831845f  // 1/sqrt(128)

// -------------------- scratch (static device allocations) ------------------
__device__ float g_x2[NTOK * DMOD];
__device__ float g_bias2d[(size_t)NTOK * NTOK];
__device__ float g_Wqkv[3 * DMOD * DMOD];
__device__ float g_bqkv[3 * DMOD];
__device__ float g_qkv[3 * NTOK * DMOD];
__device__ float g_ao[NTOK * DMOD];
__device__ float g_t[NTOK * DMOD];
__device__ float g_h1[NTOK * DMOD];
__device__ float g_ff[(size_t)NTOK * FFD];
__device__ float g_part[(size_t)6 * NTOK * DMOD];   // 48 MB split-K partials
__device__ float g_etw[64];

// -------------------- helpers ----------------------------------------------
__device__ __forceinline__ uint32_t f2tf(float f) {
    uint32_t u; asm("cvt.rna.tf32.f32 %0, %1;" : "=r"(u) : "f"(f)); return u;
}
__device__ __forceinline__ void cpasync16(uint32_t s, const void* g) {
    asm volatile("cp.async.cg.shared.global [%0], [%1], 16;" :: "r"(s), "l"(g));
}
#define COMMIT() asm volatile("cp.async.commit_group;" ::: "memory")
#define WAITG1() asm volatile("cp.async.wait_group 1;" ::: "memory")

#define BK 32
#define AFW1 4096

__device__ __forceinline__ void storeA_frag(
    uint32_t* AFb, const float4 stA[2][2], int wmS, int iS, int g, int tg)
{
#pragma unroll
    for (int h = 0; h < 2; h++) {
        const int ks4h = (tg >> 1) + 2 * h;
        const int hk = tg & 1;
#pragma unroll
        for (int cc = 0; cc < 4; cc++) {
            const int lane_sw = (g * 4 + cc) ^ (g & 3);
            const int word = (((wmS * 4 + ks4h) * 4 + iS) * 32 + lane_sw) * 4 + 2 * hk;
            uint32_t v0 = f2tf(((const float*)&stA[0][h])[cc]);
            uint32_t v1 = f2tf(((const float*)&stA[1][h])[cc]);
            *(uint2*)&AFb[word] = make_uint2(v0, v1);
        }
    }
}

#define MMA_TF32(acc, af, bf)                                              \
    asm volatile(                                                          \
        "mma.sync.aligned.m16n8k8.row.col.f32.tf32.tf32.f32 "              \
        "{%0,%1,%2,%3}, {%4,%5,%6,%7}, {%8,%9}, {%0,%1,%2,%3};"            \
        : "+f"(acc[0]), "+f"(acc[1]), "+f"(acc[2]), "+f"(acc[3])           \
        : "r"(af[0]), "r"(af[1]), "r"(af[2]), "r"(af[3]),                  \
          "r"(bf[0]), "r"(bf[1]))

// ==================== wide GEMM: CTA 128x256, warp 64x64 ====================
#define WBN 256
#define WPITCH 264
#define WBBW (32 * WPITCH)                 // 8448 words per B stage
#define WSMEM_BYTES ((2 * AFW1 + 3 * WBBW) * 4)   // 134144

__global__ __launch_bounds__(256, 1) void tgemm_wide(
    const float* __restrict__ A, const float* __restrict__ B,
    const float* __restrict__ biasvec, float* __restrict__ C,
    int M, int N, int K, size_t sA, size_t sB, size_t sC, size_t sBias,
    int doRelu, int nsplit)
{
    extern __shared__ uint32_t sm[];
    uint32_t* AF = sm;                  // 2 * AFW1
    uint32_t* BBuf = sm + 2 * AFW1;     // 3 * WBBW

    const int tid = threadIdx.x, wid = tid >> 5, lane = tid & 31;
    const int g = lane >> 2, tg = lane & 3, wm = wid >> 2, wn = wid & 3;
    const int batch = blockIdx.z / nsplit, split = blockIdx.z - batch * nsplit;
    const int Keff = K / nsplit, nIter = Keff / BK;

    const float* Ab = A + (size_t)batch * sA + (size_t)split * Keff
                        + (size_t)blockIdx.y * 128 * K;
    const float* Bb = B + (size_t)batch * sB + (size_t)split * Keff * N
                        + (size_t)blockIdx.x * WBN;
    float* Cb = C + (size_t)blockIdx.z * sC;
    const float* bvv = biasvec ? biasvec + (size_t)batch * sBias : nullptr;

    // A fill mapping (identical to verified kernel; BM=128)
    const int wmS = wid >> 2, iS = wid & 3;
    const float* Ag0 = Ab + (size_t)(wid * 16 + g) * K + tg * 4;
    const float* Ag1 = Ag0 + (size_t)8 * K;

    // B fill: 32 rows x 256 cols per stage, 256 threads x 8 x 16B
    const int bRow = tid >> 6;            // 0..3
    const int bCol = (tid & 63) << 2;     // 0..252
    const float* Bg = Bb + (size_t)bRow * N + bCol;
    const uint32_t bShared = (uint32_t)__cvta_generic_to_shared(BBuf);

    float4 stA[2][2];
    stA[0][0] = *(const float4*)(Ag0);       stA[0][1] = *(const float4*)(Ag0 + 16);
    stA[1][0] = *(const float4*)(Ag1);       stA[1][1] = *(const float4*)(Ag1 + 16);
    storeA_frag(AF, stA, wmS, iS, g, tg);
#pragma unroll
    for (int rh = 0; rh < 32; rh += 4)
        cpasync16(bShared + (((bRow + rh) * WPITCH + bCol) << 2), Bg + (size_t)rh * N);
    COMMIT();
    stA[0][0] = *(const float4*)(Ag0 + BK);  stA[0][1] = *(const float4*)(Ag0 + BK + 16);
    stA[1][0] = *(const float4*)(Ag1 + BK);  stA[1][1] = *(const float4*)(Ag1 + BK + 16);
    {
        const float* Bn = Bg + (size_t)BK * N;
        const uint32_t db = bShared + (WBBW << 2);
#pragma unroll
        for (int rh = 0; rh < 32; rh += 4)
            cpasync16(db + (((bRow + rh) * WPITCH + bCol) << 2), Bn + (size_t)rh * N);
    }
    COMMIT();

    float acc[4][8][4];
#pragma unroll
    for (int i = 0; i < 4; i++)
#pragma unroll
        for (int j = 0; j < 8; j++)
#pragma unroll
            for (int r = 0; r < 4; r++) acc[i][j][r] = 0.f;

    for (int it = 0; it < nIter; it++) {
        WAITG1();
        __syncthreads();
        if (it + 2 < nIter) {
            const float* Bn = Bg + (size_t)(it + 2) * BK * N;
            const uint32_t db = bShared + (((it + 2) % 3) * WBBW << 2);
#pragma unroll
            for (int rh = 0; rh < 32; rh += 4)
                cpasync16(db + (((bRow + rh) * WPITCH + bCol) << 2), Bn + (size_t)rh * N);
        }
        COMMIT();
        if (it + 1 < nIter)
            storeA_frag(AF + ((it + 1) & 1) * AFW1, stA, wmS, iS, g, tg);
        if (it + 2 < nIter) {
            const float* An0 = Ag0 + (size_t)(it + 2) * BK;
            const float* An1 = Ag1 + (size_t)(it + 2) * BK;
            stA[0][0] = *(const float4*)(An0);  stA[0][1] = *(const float4*)(An0 + 16);
            stA[1][0] = *(const float4*)(An1);  stA[1][1] = *(const float4*)(An1 + 16);
        }
        const uint32_t* AFr = AF + (it & 1) * AFW1;
        const uint32_t* Bs = BBuf + (it % 3) * WBBW;
#pragma unroll
        for (int ks4 = 0; ks4 < 4; ks4++) {
            uint32_t af[4][4], bf[8][2];
#pragma unroll
            for (int i = 0; i < 4; i++) {
                const uint4 qd = *(const uint4*)
                    &AFr[(((wm * 4 + ks4) * 4 + i) * 32 + (lane ^ (g & 3))) * 4];
                af[i][0] = qd.x; af[i][1] = qd.y; af[i][2] = qd.z; af[i][3] = qd.w;
            }
            const int kl = ks4 * 8 + tg;
#pragma unroll
            for (int j = 0; j < 8; j++) {
                const int c0 = wn * 64 + j * 8 + g;
                bf[j][0] = Bs[kl * WPITCH + c0];
                bf[j][1] = Bs[(kl + 4) * WPITCH + c0];
            }
#pragma unroll
            for (int i = 0; i < 4; i++)
#pragma unroll
                for (int j = 0; j < 8; j++) MMA_TF32(acc[i][j], af[i], bf[j]);
        }
        __syncthreads();
    }

#pragma unroll
    for (int i = 0; i < 4; i++) {
        const int row = blockIdx.y * 128 + wm * 64 + i * 16 + g;
#pragma unroll
        for (int j = 0; j < 8; j++) {
            const int col = blockIdx.x * WBN + wn * 64 + j * 8 + 2 * tg;
            float v0 = acc[i][j][0], v1 = acc[i][j][1];
            float v2 = acc[i][j][2], v3 = acc[i][j][3];
            if (bvv) {
                v0 += bvv[col]; v1 += bvv[col + 1];
                v2 += bvv[col]; v3 += bvv[col + 1];
            }
            if (doRelu) {
                v0 = fmaxf(v0, 0.f); v1 = fmaxf(v1, 0.f);
                v2 = fmaxf(v2, 0.f); v3 = fmaxf(v3, 0.f);
            }
            *(float2*)(Cb + (size_t)row * N + col) = make_float2(v0, v1);
            *(float2*)(Cb + (size_t)(row + 8) * N + col) = make_float2(v2, v3);
        }
    }
}

// ==================== flash attention (round-8, verified) ====================
#define BPITCH 136
#define BBW (32 * BPITCH)
#define PSP 132
#define FL_BBUF 16384
#define FL_PS   29440
#define FL_REDM 46336
#define FLASH_SMEM (47360 * 4)

__global__ __launch_bounds__(256, 1) void flash_k(
    const float* __restrict__ Q, const float* __restrict__ Km,
    const float* __restrict__ V, const float* __restrict__ bias2d,
    float* __restrict__ O)
{
    extern __shared__ uint32_t sm[];
    uint32_t* AFQ = sm;
    uint32_t* BBuf = sm + FL_BBUF;
    uint32_t* Ps = sm + FL_PS;
    float* redM = (float*)(sm + FL_REDM);
    float* redS = redM + 512;

    const int tid = threadIdx.x, wid = tid >> 5, lane = tid & 31;
    const int g = lane >> 2, tg = lane & 3, wm = wid >> 2, wn = wid & 3;
    const int h = blockIdx.z, by = blockIdx.y;
    const size_t HB = (size_t)h * 256 * DMOD;

    const float* Qh = Q + HB;
    const float* Kh = Km + HB;
    const float* Vh = V + HB;

    const int bRow = tid >> 5, bCol = (tid & 31) << 2;
    const uint32_t bSh = (uint32_t)__cvta_generic_to_shared(BBuf);
    auto issue_body = [&](int qq) {
        const int t = qq >> 3, ph = qq & 7;
        const float* src;
        int stride;
        if (ph < 4) { src = Kh + (size_t)(ph * 32 + bRow) * NTOK + t * 128 + bCol; stride = NTOK; }
        else        { src = Vh + (size_t)(t * 128 + (ph - 4) * 32 + bRow) * DKH + bCol; stride = DKH; }
        const uint32_t db = bSh + ((qq % 3) * BBW << 2);
#pragma unroll
        for (int rh = 0; rh < 32; rh += 8)
            cpasync16(db + (((bRow + rh) * BPITCH + bCol) << 2), src + (size_t)rh * stride);
    };
    issue_body(0); COMMIT();
    issue_body(1); COMMIT();

    {
        const int wmS = wid >> 2, iS = wid & 3;
        const float* Qg0 = Qh + (size_t)(by * 128 + wid * 16 + g) * DKH + tg * 4;
        const float* Qg1 = Qg0 + 8 * DKH;
#pragma unroll
        for (int c = 0; c < 4; c++) {
            float4 stA[2][2];
            stA[0][0] = *(const float4*)(Qg0 + c * 32);
            stA[0][1] = *(const float4*)(Qg0 + c * 32 + 16);
            stA[1][0] = *(const float4*)(Qg1 + c * 32);
            stA[1][1] = *(const float4*)(Qg1 + c * 32 + 16);
            storeA_frag(AFQ + c * 4096, stA, wmS, iS, g, tg);
        }
    }

    float m8[8], l8[8], oacc[4][4][4];
#pragma unroll
    for (int s = 0; s < 8; s++) { m8[s] = -1e30f; l8[s] = 0.f; }
#pragma unroll
    for (int i = 0; i < 4; i++)
#pragma unroll
        for (int j = 0; j < 4; j++)
#pragma unroll
            for (int r = 0; r < 4; r++) oacc[i][j][r] = 0.f;

    int q = 0;
    for (int t = 0; t < 16; t++) {
        float sacc[4][4][4];
#pragma unroll
        for (int i = 0; i < 4; i++)
#pragma unroll
            for (int j = 0; j < 4; j++)
#pragma unroll
                for (int r = 0; r < 4; r++) sacc[i][j][r] = 0.f;

        for (int c = 0; c < 4; c++, q++) {
            WAITG1();
            __syncthreads();
            if (q + 2 < 128) issue_body(q + 2);
            COMMIT();
            const uint32_t* AFr = AFQ + c * 4096;
            const uint32_t* Bs = BBuf + (q % 3) * BBW;
#pragma unroll
            for (int ks4 = 0; ks4 < 4; ks4++) {
                uint32_t af[4][4], bf[4][2];
#pragma unroll
                for (int i = 0; i < 4; i++) {
                    const uint4 qd = *(const uint4*)
                        &AFr[(((wm * 4 + ks4) * 4 + i) * 32 + (lane ^ (g & 3))) * 4];
                    af[i][0] = qd.x; af[i][1] = qd.y; af[i][2] = qd.z; af[i][3] = qd.w;
                }
                const int kl = ks4 * 8 + tg;
#pragma unroll
                for (int j = 0; j < 4; j++) {
                    const int c0 = wn * 32 + j * 8 + g;
                    bf[j][0] = Bs[kl * BPITCH + c0];
                    bf[j][1] = Bs[(kl + 4) * BPITCH + c0];
                }
#pragma unroll
                for (int i = 0; i < 4; i++)
#pragma unroll
                    for (int j = 0; j < 4; j++) MMA_TF32(sacc[i][j], af[i], bf[j]);
            }
            __syncthreads();
        }

#pragma unroll
        for (int i = 0; i < 4; i++) {
            const int rg = by * 128 + wm * 64 + i * 16 + g;
#pragma unroll
            for (int j = 0; j < 4; j++) {
                const int cg = t * 128 + wn * 32 + j * 8 + 2 * tg;
                const float2 b0 = *(const float2*)(bias2d + (size_t)rg * NTOK + cg);
                const float2 b1 = *(const float2*)(bias2d + (size_t)(rg + 8) * NTOK + cg);
                sacc[i][j][0] = sacc[i][j][0] * SCALE + b0.x;
                sacc[i][j][1] = sacc[i][j][1] * SCALE + b0.y;
                sacc[i][j][2] = sacc[i][j][2] * SCALE + b1.x;
                sacc[i][j][3] = sacc[i][j][3] * SCALE + b1.y;
            }
        }

        float pm[8];
#pragma unroll
        for (int i = 0; i < 4; i++)
#pragma unroll
            for (int h2 = 0; h2 < 2; h2++) {
                float v = -1e30f;
#pragma unroll
                for (int j = 0; j < 4; j++)
                    v = fmaxf(v, fmaxf(sacc[i][j][2 * h2], sacc[i][j][2 * h2 + 1]));
                pm[i * 2 + h2] = v;
            }
#pragma unroll
        for (int s = 0; s < 8; s++) {
            pm[s] = fmaxf(pm[s], __shfl_xor_sync(~0u, pm[s], 1));
            pm[s] = fmaxf(pm[s], __shfl_xor_sync(~0u, pm[s], 2));
        }
#pragma unroll
        for (int s = 0; s < 8; s++) {
            const int row = wm * 64 + (s >> 1) * 16 + (s & 1) * 8 + g;
            if (tg == 0) redM[row * 4 + wn] = pm[s];
        }
        __syncthreads();

        float alpha[8], nm[8];
#pragma unroll
        for (int s = 0; s < 8; s++) {
            const int row = wm * 64 + (s >> 1) * 16 + (s & 1) * 8 + g;
            float tm = fmaxf(fmaxf(redM[row * 4], redM[row * 4 + 1]),
                             fmaxf(redM[row * 4 + 2], redM[row * 4 + 3]));
            nm[s] = fmaxf(m8[s], tm);
            alpha[s] = __expf(m8[s] - nm[s]);
            m8[s] = nm[s];
        }

        float ps[8];
#pragma unroll
        for (int s = 0; s < 8; s++) ps[s] = 0.f;
#pragma unroll
        for (int i = 0; i < 4; i++)
#pragma unroll
            for (int h2 = 0; h2 < 2; h2++) {
                const int row = wm * 64 + i * 16 + h2 * 8 + g;
#pragma unroll
                for (int j = 0; j < 4; j++) {
                    const int col = wn * 32 + j * 8 + 2 * tg;
                    float p0 = __expf(sacc[i][j][2 * h2] - nm[i * 2 + h2]);
                    float p1 = __expf(sacc[i][j][2 * h2 + 1] - nm[i * 2 + h2]);
                    ps[i * 2 + h2] += p0 + p1;
                    *(uint2*)&Ps[row * PSP + col] =
                        make_uint2(__float_as_uint(p0), __float_as_uint(p1));
                }
            }
#pragma unroll
        for (int s = 0; s < 8; s++) {
            ps[s] += __shfl_xor_sync(~0u, ps[s], 1);
            ps[s] += __shfl_xor_sync(~0u, ps[s], 2);
            const int row = wm * 64 + (s >> 1) * 16 + (s & 1) * 8 + g;
            if (tg == 0) redS[row * 4 + wn] = ps[s];
        }
        __syncthreads();
#pragma unroll
        for (int s = 0; s < 8; s++) {
            const int row = wm * 64 + (s >> 1) * 16 + (s & 1) * 8 + g;
            const float ts = redS[row * 4] + redS[row * 4 + 1] +
                             redS[row * 4 + 2] + redS[row * 4 + 3];
            l8[s] = alpha[s] * l8[s] + ts;
        }
#pragma unroll
        for (int i = 0; i < 4; i++)
#pragma unroll
            for (int j = 0; j < 4; j++) {
                oacc[i][j][0] *= alpha[i * 2];
                oacc[i][j][1] *= alpha[i * 2];
                oacc[i][j][2] *= alpha[i * 2 + 1];
                oacc[i][j][3] *= alpha[i * 2 + 1];
            }

        for (int c = 0; c < 4; c++, q++) {
            WAITG1();
            __syncthreads();
            if (q + 2 < 128) issue_body(q + 2);
            COMMIT();
            const uint32_t* Bs = BBuf + (q % 3) * BBW;
            const int kb = c * 32;
#pragma unroll
            for (int ks4 = 0; ks4 < 4; ks4++) {
                uint32_t af[4][4], bf[4][2];
                const int kk = kb + ks4 * 8 + tg;
#pragma unroll
                for (int i = 0; i < 4; i++) {
                    const int r0 = wm * 64 + i * 16 + g;
                    af[i][0] = Ps[r0 * PSP + kk];
                    af[i][1] = Ps[(r0 + 8) * PSP + kk];
                    af[i][2] = Ps[r0 * PSP + kk + 4];
                    af[i][3] = Ps[(r0 + 8) * PSP + kk + 4];
                }
                const int kl = ks4 * 8 + tg;
#pragma unroll
                for (int j = 0; j < 4; j++) {
                    const int c0 = wn * 32 + j * 8 + g;
                    bf[j][0] = Bs[kl * BPITCH + c0];
                    bf[j][1] = Bs[(kl + 4) * BPITCH + c0];
                }
#pragma unroll
                for (int i = 0; i < 4; i++)
#pragma unroll
                    for (int j = 0; j < 4; j++) MMA_TF32(oacc[i][j], af[i], bf[j]);
            }
            __syncthreads();
        }
    }

    float* Oh = O + HB;
#pragma unroll
    for (int i = 0; i < 4; i++) {
        const int row = by * 128 + wm * 64 + i * 16 + g;
        const float inv0 = 1.f / l8[i * 2];
        const float inv1 = 1.f / l8[i * 2 + 1];
#pragma unroll
        for (int j = 0; j < 4; j++) {
            const int col = wn * 32 + j * 8 + 2 * tg;
            *(float2*)(Oh + (size_t)row * DKH + col) =
                make_float2(oacc[i][j][0] * inv0, oacc[i][j][1] * inv0);
            *(float2*)(Oh + (size_t)(row + 8) * DKH + col) =
                make_float2(oacc[i][j][2] * inv1, oacc[i][j][3] * inv1);
        }
    }
}

// ---- split-K reduce: out[b][e] = sum_s part[b][s][e] (+bias[b]) ----
__global__ void reduceK_k(const float4* __restrict__ part, float4* __restrict__ outp,
                          const float* __restrict__ bias, int nsplit, size_t MN4,
                          int N4, int sB4)
{
    const size_t i = (size_t)blockIdx.x * blockDim.x + threadIdx.x;
    const size_t b = i / MN4, e = i - b * MN4;
    const float4* p = part + b * (size_t)nsplit * MN4 + e;
    float4 a = p[0];
    for (int s = 1; s < nsplit; s++) {
        const float4 v = p[(size_t)s * MN4];
        a.x += v.x; a.y += v.y; a.z += v.z; a.w += v.w;
    }
    if (bias) {
        const float4 bb = ((const float4*)bias)[b * sB4 + (e % N4)];
        a.x += bb.x; a.y += bb.y; a.z += bb.z; a.w += bb.w;
    }
    outp[i] = a;
}

// ---- x2 = x + deg embeddings ----
__global__ void addemb_k(const float* __restrict__ x, const int* __restrict__ ind,
                         const int* __restrict__ outd, const float* __restrict__ ie,
                         const float* __restrict__ oe, float* __restrict__ x2)
{
    const int n = blockIdx.x;
    const float4* xr = (const float4*)(x + (size_t)n * DMOD);
    const float4* ir = (const float4*)(ie + (size_t)ind[n] * DMOD);
    const float4* orr = (const float4*)(oe + (size_t)outd[n] * DMOD);
    const int i = threadIdx.x;
    float4 a = xr[i], b = ir[i], c = orr[i];
    a.x += b.x + c.x; a.y += b.y + c.y; a.z += b.z + c.z; a.w += b.w + c.w;
    ((float4*)(x2 + (size_t)n * DMOD))[i] = a;
}

__global__ void etw_k(const float* __restrict__ re, const float* __restrict__ rw,
                      float* __restrict__ etw)
{
    const int t = threadIdx.x;
    float s = 0.f;
    for (int j = 0; j < DKH; j++) s += re[t * DKH + j] * rw[t * DKH + j];
    etw[t] = s * SCALE;
}

__global__ void bias2d_k(const int* __restrict__ dist, const int4* __restrict__ pet,
                         const float4* __restrict__ paw, const float* __restrict__ plen,
                         const float* __restrict__ etw, float* __restrict__ out)
{
    const size_t i = (size_t)blockIdx.x * blockDim.x + threadIdx.x;
    const int4 e = pet[i];
    const float4 w = paw[i];
    float b = plen[dist[i]];
    b += etw[e.x] * w.x + etw[e.y] * w.y + etw[e.z] * w.z + etw[e.w] * w.w;
    out[i] = b;
}

__global__ void add_ln_k(const float* __restrict__ a, const float* __restrict__ c,
                         const float* __restrict__ g, const float* __restrict__ b,
                         float* __restrict__ y)
{
    const int n = blockIdx.x;
    const float* ar = a + (size_t)n * DMOD;
    const float* cr = c + (size_t)n * DMOD;
    float* yr = y + (size_t)n * DMOD;
    __shared__ float r1[256], r2[256];
    float s = 0.f, s2 = 0.f;
    for (int i = threadIdx.x; i < DMOD; i += 256) {
        float v = ar[i] + cr[i];
        s += v; s2 += v * v;
    }
    r1[threadIdx.x] = s; r2[threadIdx.x] = s2;
    __syncthreads();
    for (int st = 128; st > 0; st >>= 1) {
        if (threadIdx.x < st) {
            r1[threadIdx.x] += r1[threadIdx.x + st];
            r2[threadIdx.x] += r2[threadIdx.x + st];
        }
        __syncthreads();
    }
    const float mean = r1[0] * (1.f / DMOD);
    const float var = r2[0] * (1.f / DMOD) - mean * mean;
    const float rstd = rsqrtf(var + 1e-5f);
    for (int i = threadIdx.x; i < DMOD; i += 256) {
        float v = ar[i] + cr[i];
        yr[i] = (v - mean) * rstd * g[i] + b[i];
    }
}

// ---------------------------------------------------------------------------
extern "C" void kernel_launch(void* const* d_in, const int* in_sizes, int n_in,
                              void* d_out, int out_size)
{
    const float* x      = (const float*)d_in[0];
    const float* lgx    = (const float*)d_in[1];
    const int* in_deg   = (const int*)d_in[2];
    const int* out_deg  = (const int*)d_in[3];
    const int* dist     = (const int*)d_in[4];
    const int* pet      = (const int*)d_in[5];
    const float* paw    = (const float*)d_in[6];
    const float* rel_e  = (const float*)d_in[7];
    const float* rel_w  = (const float*)d_in[8];
    const float* ide    = (const float*)d_in[9];
    const float* ode    = (const float*)d_in[10];
    const float* plen   = (const float*)d_in[11];
    const float* Wq = (const float*)d_in[12];  const float* bq = (const float*)d_in[13];
    const float* Wk = (const float*)d_in[14];  const float* bk = (const float*)d_in[15];
    const float* Wv = (const float*)d_in[16];  const float* bv = (const float*)d_in[17];
    const float* Wo = (const float*)d_in[18];  const float* bo = (const float*)d_in[19];
    const float* ln1g = (const float*)d_in[20]; const float* ln1b = (const float*)d_in[21];
    const float* W1 = (const float*)d_in[22];  const float* b1 = (const float*)d_in[23];
    const float* W2 = (const float*)d_in[24];  const float* b2 = (const float*)d_in[25];
    const float* ln2g = (const float*)d_in[26]; const float* ln2b = (const float*)d_in[27];
    float* out = (float*)d_out;

    float *x2, *bias2d, *Wqkv, *bqkv, *qkv, *ao, *t, *h1, *ff, *part, *etw;
    cudaGetSymbolAddress((void**)&x2, g_x2);
    cudaGetSymbolAddress((void**)&bias2d, g_bias2d);
    cudaGetSymbolAddress((void**)&Wqkv, g_Wqkv);
    cudaGetSymbolAddress((void**)&bqkv, g_bqkv);
    cudaGetSymbolAddress((void**)&qkv, g_qkv);
    cudaGetSymbolAddress((void**)&ao, g_ao);
    cudaGetSymbolAddress((void**)&t, g_t);
    cudaGetSymbolAddress((void**)&h1, g_h1);
    cudaGetSymbolAddress((void**)&ff, g_ff);
    cudaGetSymbolAddress((void**)&part, g_part);
    cudaGetSymbolAddress((void**)&etw, g_etw);

    cudaFuncSetAttribute(tgemm_wide, cudaFuncAttributeMaxDynamicSharedMemorySize,
                         WSMEM_BYTES);
    cudaFuncSetAttribute(flash_k, cudaFuncAttributeMaxDynamicSharedMemorySize,
                         FLASH_SMEM);

    // side stream + events (host resources; created once)
    static cudaStream_t s2 = nullptr;
    static cudaEvent_t evFork = nullptr, evJoin = nullptr;
    if (!s2) {
        cudaStreamCreateWithFlags(&s2, cudaStreamNonBlocking);
        cudaEventCreateWithFlags(&evFork, cudaEventDisableTiming);
        cudaEventCreateWithFlags(&evJoin, cudaEventDisableTiming);
    }

    const size_t WB = (size_t)DMOD * DMOD * sizeof(float);
    const size_t ND = (size_t)NTOK * DMOD;

    // fork: lgx copy + etw + bias2d on side stream
    cudaEventRecord(evFork, 0);
    cudaStreamWaitEvent(s2, evFork, 0);
    cudaMemcpyAsync(out + ND, lgx, (size_t)NTOK * 8 * DMOD * sizeof(float),
                    cudaMemcpyDeviceToDevice, s2);
    etw_k<<<1, 64, 0, s2>>>(rel_e, rel_w, etw);
    bias2d_k<<<(NTOK * NTOK) / 256, 256, 0, s2>>>(
        dist, (const int4*)pet, (const float4*)paw, plen, etw, bias2d);
    cudaEventRecord(evJoin, s2);

    // main stream: pack weights, addemb
    cudaMemcpyAsync(Wqkv,            Wq, WB, cudaMemcpyDeviceToDevice);
    cudaMemcpyAsync(Wqkv + WB / 4,   Wk, WB, cudaMemcpyDeviceToDevice);
    cudaMemcpyAsync(Wqkv + WB / 2,   Wv, WB, cudaMemcpyDeviceToDevice);
    cudaMemcpyAsync(bqkv,            bq, DMOD * 4, cudaMemcpyDeviceToDevice);
    cudaMemcpyAsync(bqkv + DMOD,     bk, DMOD * 4, cudaMemcpyDeviceToDevice);
    cudaMemcpyAsync(bqkv + 2 * DMOD, bv, DMOD * 4, cudaMemcpyDeviceToDevice);

    addemb_k<<<NTOK, 256>>>(x, in_deg, out_deg, ide, ode, x2);

    float* q = qkv;
    float* k = qkv + ND;
    float* v = qkv + 2 * ND;

    // QKV: wide GEMM, split-K=2, 3 batches -> partials, reduce(+bqkv)
    tgemm_wide<<<dim3(DMOD / WBN, 16, 6), 256, WSMEM_BYTES>>>(
        x2, Wqkv, nullptr, part, NTOK, DMOD, DMOD,
        0, (size_t)DMOD * DMOD, ND, 0, 0, 2);
    reduceK_k<<<(int)(3 * ND / 4 / 256), 256>>>(
        (const float4*)part, (float4*)qkv, bqkv, 2, ND / 4, DMOD / 4, DMOD / 4);

    // join: flash needs bias2d
    cudaStreamWaitEvent(0, evJoin, 0);
    flash_k<<<dim3(1, 16, HEADS), 256, FLASH_SMEM>>>(q, k, v, bias2d, ao);

    // Wo: wide GEMM split-K=2 + reduce(+bo) + LN1
    tgemm_wide<<<dim3(DMOD / WBN, 16, 2), 256, WSMEM_BYTES>>>(
        ao, Wo, nullptr, part, NTOK, DMOD, DMOD, 0, 0, ND, 0, 0, 2);
    reduceK_k<<<(int)(ND / 4 / 256), 256>>>(
        (const float4*)part, (float4*)t, bo, 2, ND / 4, DMOD / 4, 0);
    add_ln_k<<<NTOK, 256>>>(x2, t, ln1g, ln1b, h1);

    // FFN1: wide GEMM (+b1, relu)
    tgemm_wide<<<dim3(FFD / WBN, 16, 1), 256, WSMEM_BYTES>>>(
        h1, W1, b1, ff, NTOK, FFD, DMOD, 0, 0, 0, FFD, 1, 1);

    // FFN2: wide GEMM split-K=2 + reduce(+b2) + LN2
    tgemm_wide<<<dim3(DMOD / WBN, 16, 2), 256, WSMEM_BYTES>>>(
        ff, W2, nullptr, part, NTOK, DMOD, FFD, 0, 0, ND, 0, 0, 2);
    reduceK_k<<<(int)(ND / 4 / 256), 256>>>(
        (const float4*)part, (float4*)t, b2, 2, ND / 4, DMOD / 4, 0);
    add_ln_k<<<NTOK, 256>>>(h1, t, ln2g, ln2b, out);
}

// round 11
// speedup vs baseline: 1.3571x; 1.3571x over previous
#include <cuda_runtime.h>
#include <cuda_fp16.h>
#include <cstdint>
#include <cstddef>

// ---------------------------------------------------------------------------
// Rel_Transformer_Layer: N=2048, D=1024, H=8, DK=128, L=4, FF=4096
// Round 11: all GEMMs on fp16 m16n8k16 (2x FLOP/instr vs tf32 m16n8k8 at the
// measured tensor-issue ceiling). fp32 accum; fp16 rounding == tf32 (10 bits).
// ---------------------------------------------------------------------------

#define NTOK 2048
#define DMOD 1024
#define HEADS 8
#define DKH 128
#define FFD 4096
#define SCALE 0.08838834764831845f

// -------------------- scratch ------------------
__device__ float g_x2[NTOK * DMOD];
__device__ float g_bias2d[(size_t)NTOK * NTOK];
__device__ float g_bqkv[3 * DMOD];
__device__ float g_qkv[3 * NTOK * DMOD];
__device__ float g_ao[NTOK * DMOD];
__device__ float g_t[NTOK * DMOD];
__device__ float g_h1[NTOK * DMOD];
__device__ float g_ff[(size_t)NTOK * FFD];
__device__ float g_part[(size_t)6 * NTOK * DMOD];
__device__ float g_etw[64];
// packed half2 operand buffers (words)
__device__ uint32_t g_Wqp[3 * 512 * DMOD];     // [3][512][1024]
__device__ uint32_t g_Wop[512 * DMOD];
__device__ uint32_t g_W1p[512 * FFD];
__device__ uint32_t g_W2p[2048 * DMOD];
__device__ uint32_t g_Kp[HEADS * 64 * NTOK];   // [h][dk/2][tok]
__device__ uint32_t g_Vp[HEADS * 1024 * DKH];  // [h][tok/2][dk]

// -------------------- helpers ------------------
__device__ __forceinline__ uint32_t h2(float a, float b) {
    __half2 h = __floats2half2_rn(a, b);
    return *(uint32_t*)&h;
}
__device__ __forceinline__ void cpasync16(uint32_t s, const void* g) {
    asm volatile("cp.async.cg.shared.global [%0], [%1], 16;" :: "r"(s), "l"(g));
}
#define COMMIT() asm volatile("cp.async.commit_group;" ::: "memory")
#define WAITG1() asm volatile("cp.async.wait_group 1;" ::: "memory")

#define MMA_F16(acc, af, bf)                                               \
    asm volatile(                                                          \
        "mma.sync.aligned.m16n8k16.row.col.f32.f16.f16.f32 "               \
        "{%0,%1,%2,%3}, {%4,%5,%6,%7}, {%8,%9}, {%0,%1,%2,%3};"            \
        : "+f"(acc[0]), "+f"(acc[1]), "+f"(acc[2]), "+f"(acc[3])           \
        : "r"(af[0]), "r"(af[1]), "r"(af[2]), "r"(af[3]),                  \
          "r"(bf[0]), "r"(bf[1]))

// A-fragment store: BK=32 (16 kpairs, 2 ks-blocks of 8). Producer warp wid
// owns rows [wid*16, wid*16+16): thread (g,tg) rows r0=wid*16+g, r1=r0+8,
// float4s at cols tg*4 (kpairs 2tg,2tg+1) and tg*4+16 (kpairs +8,+9).
// Consumer (wm,ks,i,lane) reads uint4 {a0,a1,a2,a3} at
//   (((wm*2+ks)*4+i)*32 + (lane^(g&3)))*4.
#define AFW1H 2048
__device__ __forceinline__ void storeA_h(
    uint32_t* AFb, const float4 A0[2], const float4 A1[2],
    int wmS, int iS, int g, int tg)
{
#pragma unroll
    for (int ks = 0; ks < 2; ks++) {
        const float* f0 = (const float*)&A0[ks];
        const float* f1 = (const float*)&A1[ks];
#pragma unroll
        for (int pp = 0; pp < 2; pp++) {
            const int kp = 2 * tg + pp;          // 0..7 in block
            const int tgp = kp & 3;
            const int hk = kp >> 2;
            const uint32_t w0 = h2(f0[2 * pp], f0[2 * pp + 1]);
            const uint32_t w1 = h2(f1[2 * pp], f1[2 * pp + 1]);
            const int idx = (((wmS * 2 + ks) * 4 + iS) * 32 +
                             ((g * 4 + tgp) ^ (g & 3))) * 4 + 2 * hk;
            *(uint2*)&AFb[idx] = make_uint2(w0, w1);
        }
    }
}

// ==================== fp16 GEMM: CTA 128x128, warp 64x32 ====================
// A fp32 [M][K] (converted in-kernel), B packed half2 [K/2][N].
#define HPITCH 136
#define HBBW (16 * HPITCH)              // 2176 words per B stage
#define HSMEM_BYTES ((2 * AFW1H + 3 * HBBW) * 4)   // 42496

__global__ __launch_bounds__(256, 2) void hgemm(
    const float* __restrict__ A, const uint32_t* __restrict__ Bp,
    const float* __restrict__ biasvec, float* __restrict__ C,
    int M, int N, int K, size_t sA, size_t sBp, size_t sC, size_t sBias,
    int doRelu, int nsplit)
{
    extern __shared__ uint32_t sm[];
    uint32_t* AF = sm;                   // 2 * AFW1H
    uint32_t* BBuf = sm + 2 * AFW1H;     // 3 * HBBW

    const int tid = threadIdx.x, wid = tid >> 5, lane = tid & 31;
    const int g = lane >> 2, tg = lane & 3, wm = wid >> 2, wn = wid & 3;
    const int batch = blockIdx.z / nsplit, split = blockIdx.z - batch * nsplit;
    const int Keff = K / nsplit, nIter = Keff / 32;

    const float* Ab = A + (size_t)batch * sA + (size_t)split * Keff
                        + (size_t)blockIdx.y * 128 * K;
    const uint32_t* Bb = Bp + (size_t)batch * sBp
                        + (size_t)(split * Keff / 2) * N + (size_t)blockIdx.x * 128;
    float* Cb = C + (size_t)blockIdx.z * sC;
    const float* bvv = biasvec ? biasvec + (size_t)batch * sBias : nullptr;

    const int wmS = wid >> 2, iS = wid & 3;
    const float* Ag0 = Ab + (size_t)(wid * 16 + g) * K + tg * 4;
    const float* Ag1 = Ag0 + (size_t)8 * K;

    const int bRow = tid >> 5;            // 0..7 (rows r, r+8)
    const int bCol = (tid & 31) << 2;     // 0..124 words
    const uint32_t* Bg = Bb + (size_t)bRow * N + bCol;
    const uint32_t bSh = (uint32_t)__cvta_generic_to_shared(BBuf);

    float4 A0[2], A1[2];
    A0[0] = *(const float4*)(Ag0);       A0[1] = *(const float4*)(Ag0 + 16);
    A1[0] = *(const float4*)(Ag1);       A1[1] = *(const float4*)(Ag1 + 16);
    storeA_h(AF, A0, A1, wmS, iS, g, tg);
#pragma unroll
    for (int rh = 0; rh < 16; rh += 8)
        cpasync16(bSh + (((bRow + rh) * HPITCH + bCol) << 2), Bg + (size_t)rh * N);
    COMMIT();
    A0[0] = *(const float4*)(Ag0 + 32);  A0[1] = *(const float4*)(Ag0 + 48);
    A1[0] = *(const float4*)(Ag1 + 32);  A1[1] = *(const float4*)(Ag1 + 48);
    {
        const uint32_t* Bn = Bg + (size_t)16 * N;
        const uint32_t db = bSh + (HBBW << 2);
#pragma unroll
        for (int rh = 0; rh < 16; rh += 8)
            cpasync16(db + (((bRow + rh) * HPITCH + bCol) << 2), Bn + (size_t)rh * N);
    }
    COMMIT();

    float acc[4][4][4];
#pragma unroll
    for (int i = 0; i < 4; i++)
#pragma unroll
        for (int j = 0; j < 4; j++)
#pragma unroll
            for (int r = 0; r < 4; r++) acc[i][j][r] = 0.f;

    for (int it = 0; it < nIter; it++) {
        WAITG1();
        __syncthreads();
        if (it + 2 < nIter) {
            const uint32_t* Bn = Bg + (size_t)(it + 2) * 16 * N;
            const uint32_t db = bSh + (((it + 2) % 3) * HBBW << 2);
#pragma unroll
            for (int rh = 0; rh < 16; rh += 8)
                cpasync16(db + (((bRow + rh) * HPITCH + bCol) << 2), Bn + (size_t)rh * N);
        }
        COMMIT();
        if (it + 1 < nIter)
            storeA_h(AF + ((it + 1) & 1) * AFW1H, A0, A1, wmS, iS, g, tg);
        if (it + 2 < nIter) {
            const float* An0 = Ag0 + (size_t)(it + 2) * 32;
            const float* An1 = Ag1 + (size_t)(it + 2) * 32;
            A0[0] = *(const float4*)(An0);  A0[1] = *(const float4*)(An0 + 16);
            A1[0] = *(const float4*)(An1);  A1[1] = *(const float4*)(An1 + 16);
        }
        const uint32_t* AFr = AF + (it & 1) * AFW1H;
        const uint32_t* Bs = BBuf + (it % 3) * HBBW;
#pragma unroll
        for (int ks = 0; ks < 2; ks++) {
            uint32_t af[4][4], bf[4][2];
#pragma unroll
            for (int i = 0; i < 4; i++) {
                const uint4 qd = *(const uint4*)
                    &AFr[(((wm * 2 + ks) * 4 + i) * 32 + (lane ^ (g & 3))) * 4];
                af[i][0] = qd.x; af[i][1] = qd.y; af[i][2] = qd.z; af[i][3] = qd.w;
            }
            const int kl = ks * 8 + tg;
#pragma unroll
            for (int j = 0; j < 4; j++) {
                const int c0 = wn * 32 + j * 8 + g;
                bf[j][0] = Bs[kl * HPITCH + c0];
                bf[j][1] = Bs[(kl + 4) * HPITCH + c0];
            }
#pragma unroll
            for (int i = 0; i < 4; i++)
#pragma unroll
                for (int j = 0; j < 4; j++) MMA_F16(acc[i][j], af[i], bf[j]);
        }
        __syncthreads();
    }

#pragma unroll
    for (int i = 0; i < 4; i++) {
        const int row = blockIdx.y * 128 + wm * 64 + i * 16 + g;
#pragma unroll
        for (int j = 0; j < 4; j++) {
            const int col = blockIdx.x * 128 + wn * 32 + j * 8 + 2 * tg;
            float v0 = acc[i][j][0], v1 = acc[i][j][1];
            float v2 = acc[i][j][2], v3 = acc[i][j][3];
            if (bvv) {
                v0 += bvv[col]; v1 += bvv[col + 1];
                v2 += bvv[col]; v3 += bvv[col + 1];
            }
            if (doRelu) {
                v0 = fmaxf(v0, 0.f); v1 = fmaxf(v1, 0.f);
                v2 = fmaxf(v2, 0.f); v3 = fmaxf(v3, 0.f);
            }
            *(float2*)(Cb + (size_t)row * N + col) = make_float2(v0, v1);
            *(float2*)(Cb + (size_t)(row + 8) * N + col) = make_float2(v2, v3);
        }
    }
}

// ==================== fp16 flash attention ====================
// smem words: AFQ[4*2048] | BBuf[3*2176] | Ps[128*68] | redM[512] redS[512]
#define PSP 68
#define FL_BB  8192
#define FL_PS  14720
#define FL_RED 23424
#define FLASH_SMEM (24448 * 4)

__global__ __launch_bounds__(256, 1) void flash_h(
    const float* __restrict__ Q, const uint32_t* __restrict__ Kp,
    const uint32_t* __restrict__ Vp, const float* __restrict__ bias2d,
    float* __restrict__ O)
{
    extern __shared__ uint32_t sm[];
    uint32_t* AFQ = sm;
    uint32_t* BBuf = sm + FL_BB;
    uint32_t* Ps = sm + FL_PS;
    float* redM = (float*)(sm + FL_RED);
    float* redS = redM + 512;

    const int tid = threadIdx.x, wid = tid >> 5, lane = tid & 31;
    const int g = lane >> 2, tg = lane & 3, wm = wid >> 2, wn = wid & 3;
    const int h = blockIdx.z, by = blockIdx.y;

    const float* Qh = Q + (size_t)h * 256 * DMOD;          // [2048][128]
    const uint32_t* Kh = Kp + (size_t)h * 64 * NTOK;       // [64][2048]
    const uint32_t* Vh = Vp + (size_t)h * 1024 * DKH;      // [1024][128]

    const int bRow = tid >> 5, bCol = (tid & 31) << 2;
    const uint32_t bSh = (uint32_t)__cvta_generic_to_shared(BBuf);
    auto issue_body = [&](int qq) {
        const int t = qq >> 3, ph = qq & 7;
        const uint32_t* src;
        int stride;
        if (ph < 4) { src = Kh + (size_t)(ph * 16 + bRow) * NTOK + t * 128 + bCol; stride = NTOK; }
        else        { src = Vh + (size_t)(t * 64 + (ph - 4) * 16 + bRow) * DKH + bCol; stride = DKH; }
        const uint32_t db = bSh + ((qq % 3) * HBBW << 2);
#pragma unroll
        for (int rh = 0; rh < 16; rh += 8)
            cpasync16(db + (((bRow + rh) * HPITCH + bCol) << 2), src + (size_t)rh * stride);
    };
    issue_body(0); COMMIT();
    issue_body(1); COMMIT();

    // stage all Q fragments (4 dk-chunks)
    {
        const int wmS = wid >> 2, iS = wid & 3;
        const float* Qg0 = Qh + (size_t)(by * 128 + wid * 16 + g) * DKH + tg * 4;
        const float* Qg1 = Qg0 + 8 * DKH;
#pragma unroll
        for (int c = 0; c < 4; c++) {
            float4 A0[2], A1[2];
            A0[0] = *(const float4*)(Qg0 + c * 32);
            A0[1] = *(const float4*)(Qg0 + c * 32 + 16);
            A1[0] = *(const float4*)(Qg1 + c * 32);
            A1[1] = *(const float4*)(Qg1 + c * 32 + 16);
            storeA_h(AFQ + c * AFW1H, A0, A1, wmS, iS, g, tg);
        }
    }

    float m8[8], l8[8], oacc[4][4][4];
#pragma unroll
    for (int s = 0; s < 8; s++) { m8[s] = -1e30f; l8[s] = 0.f; }
#pragma unroll
    for (int i = 0; i < 4; i++)
#pragma unroll
        for (int j = 0; j < 4; j++)
#pragma unroll
            for (int r = 0; r < 4; r++) oacc[i][j][r] = 0.f;

    int q = 0;
    for (int t = 0; t < 16; t++) {
        float sacc[4][4][4];
#pragma unroll
        for (int i = 0; i < 4; i++)
#pragma unroll
            for (int j = 0; j < 4; j++)
#pragma unroll
                for (int r = 0; r < 4; r++) sacc[i][j][r] = 0.f;

        // S = Q @ K tile (4 dk-chunks, 2 mma-K-steps each)
        for (int c = 0; c < 4; c++, q++) {
            WAITG1();
            __syncthreads();
            if (q + 2 < 128) issue_body(q + 2);
            COMMIT();
            const uint32_t* AFr = AFQ + c * AFW1H;
            const uint32_t* Bs = BBuf + (q % 3) * HBBW;
#pragma unroll
            for (int ks = 0; ks < 2; ks++) {
                uint32_t af[4][4], bf[4][2];
#pragma unroll
                for (int i = 0; i < 4; i++) {
                    const uint4 qd = *(const uint4*)
                        &AFr[(((wm * 2 + ks) * 4 + i) * 32 + (lane ^ (g & 3))) * 4];
                    af[i][0] = qd.x; af[i][1] = qd.y; af[i][2] = qd.z; af[i][3] = qd.w;
                }
                const int kl = ks * 8 + tg;
#pragma unroll
                for (int j = 0; j < 4; j++) {
                    const int c0 = wn * 32 + j * 8 + g;
                    bf[j][0] = Bs[kl * HPITCH + c0];
                    bf[j][1] = Bs[(kl + 4) * HPITCH + c0];
                }
#pragma unroll
                for (int i = 0; i < 4; i++)
#pragma unroll
                    for (int j = 0; j < 4; j++) MMA_F16(sacc[i][j], af[i], bf[j]);
            }
            __syncthreads();
        }

        // scale + bias
#pragma unroll
        for (int i = 0; i < 4; i++) {
            const int rg = by * 128 + wm * 64 + i * 16 + g;
#pragma unroll
            for (int j = 0; j < 4; j++) {
                const int cg = t * 128 + wn * 32 + j * 8 + 2 * tg;
                const float2 b0 = *(const float2*)(bias2d + (size_t)rg * NTOK + cg);
                const float2 b1 = *(const float2*)(bias2d + (size_t)(rg + 8) * NTOK + cg);
                sacc[i][j][0] = sacc[i][j][0] * SCALE + b0.x;
                sacc[i][j][1] = sacc[i][j][1] * SCALE + b0.y;
                sacc[i][j][2] = sacc[i][j][2] * SCALE + b1.x;
                sacc[i][j][3] = sacc[i][j][3] * SCALE + b1.y;
            }
        }

        // online softmax
        float pm[8];
#pragma unroll
        for (int i = 0; i < 4; i++)
#pragma unroll
            for (int h2i = 0; h2i < 2; h2i++) {
                float v = -1e30f;
#pragma unroll
                for (int j = 0; j < 4; j++)
                    v = fmaxf(v, fmaxf(sacc[i][j][2 * h2i], sacc[i][j][2 * h2i + 1]));
                pm[i * 2 + h2i] = v;
            }
#pragma unroll
        for (int s = 0; s < 8; s++) {
            pm[s] = fmaxf(pm[s], __shfl_xor_sync(~0u, pm[s], 1));
            pm[s] = fmaxf(pm[s], __shfl_xor_sync(~0u, pm[s], 2));
        }
#pragma unroll
        for (int s = 0; s < 8; s++) {
            const int row = wm * 64 + (s >> 1) * 16 + (s & 1) * 8 + g;
            if (tg == 0) redM[row * 4 + wn] = pm[s];
        }
        __syncthreads();

        float alpha[8], nm[8];
#pragma unroll
        for (int s = 0; s < 8; s++) {
            const int row = wm * 64 + (s >> 1) * 16 + (s & 1) * 8 + g;
            float tm = fmaxf(fmaxf(redM[row * 4], redM[row * 4 + 1]),
                             fmaxf(redM[row * 4 + 2], redM[row * 4 + 3]));
            nm[s] = fmaxf(m8[s], tm);
            alpha[s] = __expf(m8[s] - nm[s]);
            m8[s] = nm[s];
        }

        float ps[8];
#pragma unroll
        for (int s = 0; s < 8; s++) ps[s] = 0.f;
#pragma unroll
        for (int i = 0; i < 4; i++)
#pragma unroll
            for (int h2i = 0; h2i < 2; h2i++) {
                const int row = wm * 64 + i * 16 + h2i * 8 + g;
#pragma unroll
                for (int j = 0; j < 4; j++) {
                    const int cw = wn * 16 + j * 4 + tg;  // half2 word col
                    float p0 = __expf(sacc[i][j][2 * h2i] - nm[i * 2 + h2i]);
                    float p1 = __expf(sacc[i][j][2 * h2i + 1] - nm[i * 2 + h2i]);
                    ps[i * 2 + h2i] += p0 + p1;
                    Ps[row * PSP + cw] = h2(p0, p1);
                }
            }
#pragma unroll
        for (int s = 0; s < 8; s++) {
            ps[s] += __shfl_xor_sync(~0u, ps[s], 1);
            ps[s] += __shfl_xor_sync(~0u, ps[s], 2);
            const int row = wm * 64 + (s >> 1) * 16 + (s & 1) * 8 + g;
            if (tg == 0) redS[row * 4 + wn] = ps[s];
        }
        __syncthreads();
#pragma unroll
        for (int s = 0; s < 8; s++) {
            const int row = wm * 64 + (s >> 1) * 16 + (s & 1) * 8 + g;
            const float ts = redS[row * 4] + redS[row * 4 + 1] +
                             redS[row * 4 + 2] + redS[row * 4 + 3];
            l8[s] = alpha[s] * l8[s] + ts;
        }
#pragma unroll
        for (int i = 0; i < 4; i++)
#pragma unroll
            for (int j = 0; j < 4; j++) {
                oacc[i][j][0] *= alpha[i * 2];
                oacc[i][j][1] *= alpha[i * 2];
                oacc[i][j][2] *= alpha[i * 2 + 1];
                oacc[i][j][3] *= alpha[i * 2 + 1];
            }

        // O += P @ V tile (4 token-chunks, 2 mma-K-steps each)
        for (int c = 0; c < 4; c++, q++) {
            WAITG1();
            __syncthreads();
            if (q + 2 < 128) issue_body(q + 2);
            COMMIT();
            const uint32_t* Bs = BBuf + (q % 3) * HBBW;
#pragma unroll
            for (int ks = 0; ks < 2; ks++) {
                uint32_t af[4][4], bf[4][2];
                const int kk = c * 16 + ks * 8 + tg;   // kpair index in tile
#pragma unroll
                for (int i = 0; i < 4; i++) {
                    const int r0 = wm * 64 + i * 16 + g;
                    af[i][0] = Ps[r0 * PSP + kk];
                    af[i][1] = Ps[(r0 + 8) * PSP + kk];
                    af[i][2] = Ps[r0 * PSP + kk + 4];
                    af[i][3] = Ps[(r0 + 8) * PSP + kk + 4];
                }
                const int kl = ks * 8 + tg;
#pragma unroll
                for (int j = 0; j < 4; j++) {
                    const int c0 = wn * 32 + j * 8 + g;
                    bf[j][0] = Bs[kl * HPITCH + c0];
                    bf[j][1] = Bs[(kl + 4) * HPITCH + c0];
                }
#pragma unroll
                for (int i = 0; i < 4; i++)
#pragma unroll
                    for (int j = 0; j < 4; j++) MMA_F16(oacc[i][j], af[i], bf[j]);
            }
            __syncthreads();
        }
    }

    float* Oh = O + (size_t)h * 256 * DMOD;
#pragma unroll
    for (int i = 0; i < 4; i++) {
        const int row = by * 128 + wm * 64 + i * 16 + g;
        const float inv0 = 1.f / l8[i * 2];
        const float inv1 = 1.f / l8[i * 2 + 1];
#pragma unroll
        for (int j = 0; j < 4; j++) {
            const int col = wn * 32 + j * 8 + 2 * tg;
            *(float2*)(Oh + (size_t)row * DKH + col) =
                make_float2(oacc[i][j][0] * inv0, oacc[i][j][1] * inv0);
            *(float2*)(Oh + (size_t)(row + 8) * DKH + col) =
                make_float2(oacc[i][j][2] * inv1, oacc[i][j][3] * inv1);
        }
    }
}

// ---- weight pack: Wp[k2][n] = half2(W[2k2][n], W[2k2+1][n]) ----
__global__ void packW_k(const float* __restrict__ W, uint32_t* __restrict__ Wp, int N)
{
    const size_t i = (size_t)blockIdx.x * 256 + threadIdx.x;
    const size_t k2 = i / N, n = i - k2 * N;
    Wp[i] = h2(W[2 * k2 * N + n], W[(2 * k2 + 1) * N + n]);
}

// ---- K/V repack to half2 (pairs along dk for K, along token for V) ----
__global__ void packKV_k(const float* __restrict__ qkv,
                         uint32_t* __restrict__ Kp, uint32_t* __restrict__ Vp)
{
    const size_t i = (size_t)blockIdx.x * 256 + threadIdx.x;
    const size_t ND = (size_t)NTOK * DMOD;
    if (blockIdx.z == 0) {  // K: [h][64][2048]
        const int hh = (int)(i >> 17);           // /131072
        const size_t r = i & 131071;
        const size_t d2 = r >> 11, tk = r & 2047;
        const float* base = qkv + ND + (size_t)hh * 256 * DMOD;
        Kp[i] = h2(base[2 * d2 * 2048 + tk], base[(2 * d2 + 1) * 2048 + tk]);
    } else {                // V: [h][1024][128]
        const int hh = (int)(i >> 17);
        const size_t r = i & 131071;
        const size_t t2 = r >> 7, d = r & 127;
        const float* base = qkv + 2 * ND + (size_t)hh * 256 * DMOD;
        Vp[i] = h2(base[2 * t2 * 128 + d], base[(2 * t2 + 1) * 128 + d]);
    }
}

// ---- split-K reduce ----
__global__ void reduceK_k(const float4* __restrict__ part, float4* __restrict__ outp,
                          const float* __restrict__ bias, int nsplit, size_t MN4,
                          int N4, int sB4)
{
    const size_t i = (size_t)blockIdx.x * blockDim.x + threadIdx.x;
    const size_t b = i / MN4, e = i - b * MN4;
    const float4* p = part + b * (size_t)nsplit * MN4 + e;
    float4 a = p[0];
    for (int s = 1; s < nsplit; s++) {
        const float4 v = p[(size_t)s * MN4];
        a.x += v.x; a.y += v.y; a.z += v.z; a.w += v.w;
    }
    if (bias) {
        const float4 bb = ((const float4*)bias)[b * sB4 + (e % N4)];
        a.x += bb.x; a.y += bb.y; a.z += bb.z; a.w += bb.w;
    }
    outp[i] = a;
}

__global__ void addemb_k(const float* __restrict__ x, const int* __restrict__ ind,
                         const int* __restrict__ outd, const float* __restrict__ ie,
                         const float* __restrict__ oe, float* __restrict__ x2)
{
    const int n = blockIdx.x;
    const float4* xr = (const float4*)(x + (size_t)n * DMOD);
    const float4* ir = (const float4*)(ie + (size_t)ind[n] * DMOD);
    const float4* orr = (const float4*)(oe + (size_t)outd[n] * DMOD);
    const int i = threadIdx.x;
    float4 a = xr[i], b = ir[i], c = orr[i];
    a.x += b.x + c.x; a.y += b.y + c.y; a.z += b.z + c.z; a.w += b.w + c.w;
    ((float4*)(x2 + (size_t)n * DMOD))[i] = a;
}

__global__ void etw_k(const float* __restrict__ re, const float* __restrict__ rw,
                      float* __restrict__ etw)
{
    const int t = threadIdx.x;
    float s = 0.f;
    for (int j = 0; j < DKH; j++) s += re[t * DKH + j] * rw[t * DKH + j];
    etw[t] = s * SCALE;
}

__global__ void bias2d_k(const int* __restrict__ dist, const int4* __restrict__ pet,
                         const float4* __restrict__ paw, const float* __restrict__ plen,
                         const float* __restrict__ etw, float* __restrict__ out)
{
    const size_t i = (size_t)blockIdx.x * blockDim.x + threadIdx.x;
    const int4 e = pet[i];
    const float4 w = paw[i];
    float b = plen[dist[i]];
    b += etw[e.x] * w.x + etw[e.y] * w.y + etw[e.z] * w.z + etw[e.w] * w.w;
    out[i] = b;
}

__global__ void add_ln_k(const float* __restrict__ a, const float* __restrict__ c,
                         const float* __restrict__ g, const float* __restrict__ b,
                         float* __restrict__ y)
{
    const int n = blockIdx.x;
    const float* ar = a + (size_t)n * DMOD;
    const float* cr = c + (size_t)n * DMOD;
    float* yr = y + (size_t)n * DMOD;
    __shared__ float r1[256], r2[256];
    float s = 0.f, s2 = 0.f;
    for (int i = threadIdx.x; i < DMOD; i += 256) {
        float v = ar[i] + cr[i];
        s += v; s2 += v * v;
    }
    r1[threadIdx.x] = s; r2[threadIdx.x] = s2;
    __syncthreads();
    for (int st = 128; st > 0; st >>= 1) {
        if (threadIdx.x < st) {
            r1[threadIdx.x] += r1[threadIdx.x + st];
            r2[threadIdx.x] += r2[threadIdx.x + st];
        }
        __syncthreads();
    }
    const float mean = r1[0] * (1.f / DMOD);
    const float var = r2[0] * (1.f / DMOD) - mean * mean;
    const float rstd = rsqrtf(var + 1e-5f);
    for (int i = threadIdx.x; i < DMOD; i += 256) {
        float v = ar[i] + cr[i];
        yr[i] = (v - mean) * rstd * g[i] + b[i];
    }
}

// ---------------------------------------------------------------------------
extern "C" void kernel_launch(void* const* d_in, const int* in_sizes, int n_in,
                              void* d_out, int out_size)
{
    const float* x      = (const float*)d_in[0];
    const float* lgx    = (const float*)d_in[1];
    const int* in_deg   = (const int*)d_in[2];
    const int* out_deg  = (const int*)d_in[3];
    const int* dist     = (const int*)d_in[4];
    const int* pet      = (const int*)d_in[5];
    const float* paw    = (const float*)d_in[6];
    const float* rel_e  = (const float*)d_in[7];
    const float* rel_w  = (const float*)d_in[8];
    const float* ide    = (const float*)d_in[9];
    const float* ode    = (const float*)d_in[10];
    const float* plen   = (const float*)d_in[11];
    const float* Wq = (const float*)d_in[12];  const float* bq = (const float*)d_in[13];
    const float* Wk = (const float*)d_in[14];  const float* bk = (const float*)d_in[15];
    const float* Wv = (const float*)d_in[16];  const float* bv = (const float*)d_in[17];
    const float* Wo = (const float*)d_in[18];  const float* bo = (const float*)d_in[19];
    const float* ln1g = (const float*)d_in[20]; const float* ln1b = (const float*)d_in[21];
    const float* W1 = (const float*)d_in[22];  const float* b1 = (const float*)d_in[23];
    const float* W2 = (const float*)d_in[24];  const float* b2 = (const float*)d_in[25];
    const float* ln2g = (const float*)d_in[26]; const float* ln2b = (const float*)d_in[27];
    float* out = (float*)d_out;

    float *x2, *bias2d, *bqkv, *qkv, *ao, *t, *h1, *ff, *part, *etw;
    uint32_t *Wqp, *Wop, *W1p, *W2p, *Kp, *Vp;
    cudaGetSymbolAddress((void**)&x2, g_x2);
    cudaGetSymbolAddress((void**)&bias2d, g_bias2d);
    cudaGetSymbolAddress((void**)&bqkv, g_bqkv);
    cudaGetSymbolAddress((void**)&qkv, g_qkv);
    cudaGetSymbolAddress((void**)&ao, g_ao);
    cudaGetSymbolAddress((void**)&t, g_t);
    cudaGetSymbolAddress((void**)&h1, g_h1);
    cudaGetSymbolAddress((void**)&ff, g_ff);
    cudaGetSymbolAddress((void**)&part, g_part);
    cudaGetSymbolAddress((void**)&etw, g_etw);
    cudaGetSymbolAddress((void**)&Wqp, g_Wqp);
    cudaGetSymbolAddress((void**)&Wop, g_Wop);
    cudaGetSymbolAddress((void**)&W1p, g_W1p);
    cudaGetSymbolAddress((void**)&W2p, g_W2p);
    cudaGetSymbolAddress((void**)&Kp, g_Kp);
    cudaGetSymbolAddress((void**)&Vp, g_Vp);

    cudaFuncSetAttribute(hgemm, cudaFuncAttributeMaxDynamicSharedMemorySize,
                         HSMEM_BYTES);
    cudaFuncSetAttribute(flash_h, cudaFuncAttributeMaxDynamicSharedMemorySize,
                         FLASH_SMEM);

    static cudaStream_t s2 = nullptr;
    static cudaEvent_t evFork = nullptr, evJoin = nullptr;
    if (!s2) {
        cudaStreamCreateWithFlags(&s2, cudaStreamNonBlocking);
        cudaEventCreateWithFlags(&evFork, cudaEventDisableTiming);
        cudaEventCreateWithFlags(&evJoin, cudaEventDisableTiming);
    }

    const size_t ND = (size_t)NTOK * DMOD;

    // fork: lgx copy + etw + bias2d on side stream
    cudaEventRecord(evFork, 0);
    cudaStreamWaitEvent(s2, evFork, 0);
    cudaMemcpyAsync(out + ND, lgx, (size_t)NTOK * 8 * DMOD * sizeof(float),
                    cudaMemcpyDeviceToDevice, s2);
    etw_k<<<1, 64, 0, s2>>>(rel_e, rel_w, etw);
    bias2d_k<<<(NTOK * NTOK) / 256, 256, 0, s2>>>(
        dist, (const int4*)pet, (const float4*)paw, plen, etw, bias2d);
    cudaEventRecord(evJoin, s2);

    // main: pack weights (half2), biases, addemb
    const int WQW = 512 * DMOD;           // words per packed 1024x1024
    packW_k<<<WQW / 256, 256>>>(Wq, Wqp, DMOD);
    packW_k<<<WQW / 256, 256>>>(Wk, Wqp + WQW, DMOD);
    packW_k<<<WQW / 256, 256>>>(Wv, Wqp + 2 * WQW, DMOD);
    packW_k<<<WQW / 256, 256>>>(Wo, Wop, DMOD);
    packW_k<<<512 * FFD / 256, 256>>>(W1, W1p, FFD);
    packW_k<<<2048 * DMOD / 256, 256>>>(W2, W2p, DMOD);
    cudaMemcpyAsync(bqkv,            bq, DMOD * 4, cudaMemcpyDeviceToDevice);
    cudaMemcpyAsync(bqkv + DMOD,     bk, DMOD * 4, cudaMemcpyDeviceToDevice);
    cudaMemcpyAsync(bqkv + 2 * DMOD, bv, DMOD * 4, cudaMemcpyDeviceToDevice);
    addemb_k<<<NTOK, 256>>>(x, in_deg, out_deg, ide, ode, x2);

    float* q = qkv;

    // QKV: fp16 GEMM split-K=2, 3 batches -> partials, reduce(+bqkv)
    hgemm<<<dim3(8, 16, 6), 256, HSMEM_BYTES>>>(
        x2, Wqp, nullptr, part, NTOK, DMOD, DMOD,
        0, (size_t)WQW, ND, 0, 0, 2);
    reduceK_k<<<(int)(3 * ND / 4 / 256), 256>>>(
        (const float4*)part, (float4*)qkv, bqkv, 2, ND / 4, DMOD / 4, DMOD / 4);

    // repack K,V to half2
    packKV_k<<<dim3(HEADS * 64 * NTOK / 256, 1, 2), 256>>>(qkv, Kp, Vp);

    // join: flash needs bias2d
    cudaStreamWaitEvent(0, evJoin, 0);
    flash_h<<<dim3(1, 16, HEADS), 256, FLASH_SMEM>>>(q, Kp, Vp, bias2d, ao);

    // Wo: split-K=2 + reduce(+bo) + LN1
    hgemm<<<dim3(8, 16, 2), 256, HSMEM_BYTES>>>(
        ao, Wop, nullptr, part, NTOK, DMOD, DMOD, 0, 0, ND, 0, 0, 2);
    reduceK_k<<<(int)(ND / 4 / 256), 256>>>(
        (const float4*)part, (float4*)t, bo, 2, ND / 4, DMOD / 4, 0);
    add_ln_k<<<NTOK, 256>>>(x2, t, ln1g, ln1b, h1);

    // FFN1 (+b1, relu)
    hgemm<<<dim3(32, 16, 1), 256, HSMEM_BYTES>>>(
        h1, W1p, b1, ff, NTOK, FFD, DMOD, 0, 0, 0, FFD, 1, 1);
    // FFN2: split-K=2 + reduce(+b2) + LN2
    hgemm<<<dim3(8, 16, 2), 256, HSMEM_BYTES>>>(
        ff, W2p, nullptr, part, NTOK, DMOD, FFD, 0, 0, ND, 0, 0, 2);
    reduceK_k<<<(int)(ND / 4 / 256), 256>>>(
        (const float4*)part, (float4*)t, b2, 2, ND / 4, DMOD / 4, 0);
    add_ln_k<<<NTOK, 256>>>(h1, t, ln2g, ln2b, out);
}

// round 12
// speedup vs baseline: 1.4377x; 1.0594x over previous
#include <cuda_runtime.h>
#include <cuda_fp16.h>
#include <cstdint>
#include <cstddef>

// ---------------------------------------------------------------------------
// Rel_Transformer_Layer: N=2048, D=1024, H=8, DK=128, L=4, FF=4096
// Round 12: fp16 m16n8k16 pipeline (R11) + flash with 32-row stream chunks
// (half the barriers) + fused splitK-reduce+residual+LayerNorm tails.
// ---------------------------------------------------------------------------

#define NTOK 2048
#define DMOD 1024
#define HEADS 8
#define DKH 128
#define FFD 4096
#define SCALE 0.08838834764831845f

// -------------------- scratch ------------------
__device__ float g_x2[NTOK * DMOD];
__device__ float g_bias2d[(size_t)NTOK * NTOK];
__device__ float g_bqkv[3 * DMOD];
__device__ float g_qkv[3 * NTOK * DMOD];
__device__ float g_ao[NTOK * DMOD];
__device__ float g_h1[NTOK * DMOD];
__device__ float g_ff[(size_t)NTOK * FFD];
__device__ float g_part[(size_t)6 * NTOK * DMOD];
__device__ float g_etw[64];
__device__ uint32_t g_Wqp[3 * 512 * DMOD];
__device__ uint32_t g_Wop[512 * DMOD];
__device__ uint32_t g_W1p[512 * FFD];
__device__ uint32_t g_W2p[2048 * DMOD];
__device__ uint32_t g_Kp[HEADS * 64 * NTOK];   // [h][dk/2][tok]
__device__ uint32_t g_Vp[HEADS * 1024 * DKH];  // [h][tok/2][dk]

// -------------------- helpers ------------------
__device__ __forceinline__ uint32_t h2(float a, float b) {
    __half2 h = __floats2half2_rn(a, b);
    return *(uint32_t*)&h;
}
__device__ __forceinline__ void cpasync16(uint32_t s, const void* g) {
    asm volatile("cp.async.cg.shared.global [%0], [%1], 16;" :: "r"(s), "l"(g));
}
#define COMMIT() asm volatile("cp.async.commit_group;" ::: "memory")
#define WAITG1() asm volatile("cp.async.wait_group 1;" ::: "memory")

#define MMA_F16(acc, af, bf)                                               \
    asm volatile(                                                          \
        "mma.sync.aligned.m16n8k16.row.col.f32.f16.f16.f32 "               \
        "{%0,%1,%2,%3}, {%4,%5,%6,%7}, {%8,%9}, {%0,%1,%2,%3};"            \
        : "+f"(acc[0]), "+f"(acc[1]), "+f"(acc[2]), "+f"(acc[3])           \
        : "r"(af[0]), "r"(af[1]), "r"(af[2]), "r"(af[3]),                  \
          "r"(bf[0]), "r"(bf[1]))

#define AFW1H 2048
__device__ __forceinline__ void storeA_h(
    uint32_t* AFb, const float4 A0[2], const float4 A1[2],
    int wmS, int iS, int g, int tg)
{
#pragma unroll
    for (int ks = 0; ks < 2; ks++) {
        const float* f0 = (const float*)&A0[ks];
        const float* f1 = (const float*)&A1[ks];
#pragma unroll
        for (int pp = 0; pp < 2; pp++) {
            const int kp = 2 * tg + pp;
            const int tgp = kp & 3;
            const int hk = kp >> 2;
            const uint32_t w0 = h2(f0[2 * pp], f0[2 * pp + 1]);
            const uint32_t w1 = h2(f1[2 * pp], f1[2 * pp + 1]);
            const int idx = (((wmS * 2 + ks) * 4 + iS) * 32 +
                             ((g * 4 + tgp) ^ (g & 3))) * 4 + 2 * hk;
            *(uint2*)&AFb[idx] = make_uint2(w0, w1);
        }
    }
}

// ==================== fp16 GEMM (round-11 verified) ====================
#define HPITCH 136
#define HBBW (16 * HPITCH)
#define HSMEM_BYTES ((2 * AFW1H + 3 * HBBW) * 4)

__global__ __launch_bounds__(256, 2) void hgemm(
    const float* __restrict__ A, const uint32_t* __restrict__ Bp,
    const float* __restrict__ biasvec, float* __restrict__ C,
    int M, int N, int K, size_t sA, size_t sBp, size_t sC, size_t sBias,
    int doRelu, int nsplit)
{
    extern __shared__ uint32_t sm[];
    uint32_t* AF = sm;
    uint32_t* BBuf = sm + 2 * AFW1H;

    const int tid = threadIdx.x, wid = tid >> 5, lane = tid & 31;
    const int g = lane >> 2, tg = lane & 3, wm = wid >> 2, wn = wid & 3;
    const int batch = blockIdx.z / nsplit, split = blockIdx.z - batch * nsplit;
    const int Keff = K / nsplit, nIter = Keff / 32;

    const float* Ab = A + (size_t)batch * sA + (size_t)split * Keff
                        + (size_t)blockIdx.y * 128 * K;
    const uint32_t* Bb = Bp + (size_t)batch * sBp
                        + (size_t)(split * Keff / 2) * N + (size_t)blockIdx.x * 128;
    float* Cb = C + (size_t)blockIdx.z * sC;
    const float* bvv = biasvec ? biasvec + (size_t)batch * sBias : nullptr;

    const int wmS = wid >> 2, iS = wid & 3;
    const float* Ag0 = Ab + (size_t)(wid * 16 + g) * K + tg * 4;
    const float* Ag1 = Ag0 + (size_t)8 * K;

    const int bRow = tid >> 5;
    const int bCol = (tid & 31) << 2;
    const uint32_t* Bg = Bb + (size_t)bRow * N + bCol;
    const uint32_t bSh = (uint32_t)__cvta_generic_to_shared(BBuf);

    float4 A0[2], A1[2];
    A0[0] = *(const float4*)(Ag0);       A0[1] = *(const float4*)(Ag0 + 16);
    A1[0] = *(const float4*)(Ag1);       A1[1] = *(const float4*)(Ag1 + 16);
    storeA_h(AF, A0, A1, wmS, iS, g, tg);
#pragma unroll
    for (int rh = 0; rh < 16; rh += 8)
        cpasync16(bSh + (((bRow + rh) * HPITCH + bCol) << 2), Bg + (size_t)rh * N);
    COMMIT();
    A0[0] = *(const float4*)(Ag0 + 32);  A0[1] = *(const float4*)(Ag0 + 48);
    A1[0] = *(const float4*)(Ag1 + 32);  A1[1] = *(const float4*)(Ag1 + 48);
    {
        const uint32_t* Bn = Bg + (size_t)16 * N;
        const uint32_t db = bSh + (HBBW << 2);
#pragma unroll
        for (int rh = 0; rh < 16; rh += 8)
            cpasync16(db + (((bRow + rh) * HPITCH + bCol) << 2), Bn + (size_t)rh * N);
    }
    COMMIT();

    float acc[4][4][4];
#pragma unroll
    for (int i = 0; i < 4; i++)
#pragma unroll
        for (int j = 0; j < 4; j++)
#pragma unroll
            for (int r = 0; r < 4; r++) acc[i][j][r] = 0.f;

    for (int it = 0; it < nIter; it++) {
        WAITG1();
        __syncthreads();
        if (it + 2 < nIter) {
            const uint32_t* Bn = Bg + (size_t)(it + 2) * 16 * N;
            const uint32_t db = bSh + (((it + 2) % 3) * HBBW << 2);
#pragma unroll
            for (int rh = 0; rh < 16; rh += 8)
                cpasync16(db + (((bRow + rh) * HPITCH + bCol) << 2), Bn + (size_t)rh * N);
        }
        COMMIT();
        if (it + 1 < nIter)
            storeA_h(AF + ((it + 1) & 1) * AFW1H, A0, A1, wmS, iS, g, tg);
        if (it + 2 < nIter) {
            const float* An0 = Ag0 + (size_t)(it + 2) * 32;
            const float* An1 = Ag1 + (size_t)(it + 2) * 32;
            A0[0] = *(const float4*)(An0);  A0[1] = *(const float4*)(An0 + 16);
            A1[0] = *(const float4*)(An1);  A1[1] = *(const float4*)(An1 + 16);
        }
        const uint32_t* AFr = AF + (it & 1) * AFW1H;
        const uint32_t* Bs = BBuf + (it % 3) * HBBW;
#pragma unroll
        for (int ks = 0; ks < 2; ks++) {
            uint32_t af[4][4], bf[4][2];
#pragma unroll
            for (int i = 0; i < 4; i++) {
                const uint4 qd = *(const uint4*)
                    &AFr[(((wm * 2 + ks) * 4 + i) * 32 + (lane ^ (g & 3))) * 4];
                af[i][0] = qd.x; af[i][1] = qd.y; af[i][2] = qd.z; af[i][3] = qd.w;
            }
            const int kl = ks * 8 + tg;
#pragma unroll
            for (int j = 0; j < 4; j++) {
                const int c0 = wn * 32 + j * 8 + g;
                bf[j][0] = Bs[kl * HPITCH + c0];
                bf[j][1] = Bs[(kl + 4) * HPITCH + c0];
            }
#pragma unroll
            for (int i = 0; i < 4; i++)
#pragma unroll
                for (int j = 0; j < 4; j++) MMA_F16(acc[i][j], af[i], bf[j]);
        }
        __syncthreads();
    }

#pragma unroll
    for (int i = 0; i < 4; i++) {
        const int row = blockIdx.y * 128 + wm * 64 + i * 16 + g;
#pragma unroll
        for (int j = 0; j < 4; j++) {
            const int col = blockIdx.x * 128 + wn * 32 + j * 8 + 2 * tg;
            float v0 = acc[i][j][0], v1 = acc[i][j][1];
            float v2 = acc[i][j][2], v3 = acc[i][j][3];
            if (bvv) {
                v0 += bvv[col]; v1 += bvv[col + 1];
                v2 += bvv[col]; v3 += bvv[col + 1];
            }
            if (doRelu) {
                v0 = fmaxf(v0, 0.f); v1 = fmaxf(v1, 0.f);
                v2 = fmaxf(v2, 0.f); v3 = fmaxf(v3, 0.f);
            }
            *(float2*)(Cb + (size_t)row * N + col) = make_float2(v0, v1);
            *(float2*)(Cb + (size_t)(row + 8) * N + col) = make_float2(v2, v3);
        }
    }
}

// ==================== fp16 flash, 32-row stream chunks ====================
// smem words: AFQ[8192] | BBuf[3*4352] | Ps[128*68] | redM[512] redS[512]
#define FBBW (32 * HPITCH)            // 4352
#define PSP 68
#define FL_BB  8192
#define FL_PS  (FL_BB + 3 * FBBW)     // 21248
#define FL_RED (FL_PS + 128 * PSP)    // 29952
#define FLASH_SMEM ((FL_RED + 1024) * 4)   // 123904

__global__ __launch_bounds__(256, 1) void flash_h(
    const float* __restrict__ Q, const uint32_t* __restrict__ Kp,
    const uint32_t* __restrict__ Vp, const float* __restrict__ bias2d,
    float* __restrict__ O)
{
    extern __shared__ uint32_t sm[];
    uint32_t* AFQ = sm;
    uint32_t* BBuf = sm + FL_BB;
    uint32_t* Ps = sm + FL_PS;
    float* redM = (float*)(sm + FL_RED);
    float* redS = redM + 512;

    const int tid = threadIdx.x, wid = tid >> 5, lane = tid & 31;
    const int g = lane >> 2, tg = lane & 3, wm = wid >> 2, wn = wid & 3;
    const int h = blockIdx.z, by = blockIdx.y;

    const float* Qh = Q + (size_t)h * 256 * DMOD;
    const uint32_t* Kh = Kp + (size_t)h * 64 * NTOK;
    const uint32_t* Vh = Vp + (size_t)h * 1024 * DKH;

    const int bRow = tid >> 5, bCol = (tid & 31) << 2;
    const uint32_t bSh = (uint32_t)__cvta_generic_to_shared(BBuf);
    // chunk qq: tile t = qq>>2, phase ph = qq&3 (0..1: K 32-row halves,
    // 2..3: V 32-row halves). Each thread fills rows bRow+{0,8,16,24}.
    auto issue_body = [&](int qq) {
        const int t = qq >> 2, ph = qq & 3;
        const uint32_t* src;
        int stride;
        if (ph < 2) { src = Kh + (size_t)(ph * 32 + bRow) * NTOK + t * 128 + bCol; stride = NTOK; }
        else        { src = Vh + (size_t)(t * 64 + (ph - 2) * 32 + bRow) * DKH + bCol; stride = DKH; }
        const uint32_t db = bSh + ((qq % 3) * FBBW << 2);
#pragma unroll
        for (int rh = 0; rh < 32; rh += 8)
            cpasync16(db + (((bRow + rh) * HPITCH + bCol) << 2), src + (size_t)rh * stride);
    };
    issue_body(0); COMMIT();
    issue_body(1); COMMIT();

    {
        const int wmS = wid >> 2, iS = wid & 3;
        const float* Qg0 = Qh + (size_t)(by * 128 + wid * 16 + g) * DKH + tg * 4;
        const float* Qg1 = Qg0 + 8 * DKH;
#pragma unroll
        for (int c = 0; c < 4; c++) {
            float4 A0[2], A1[2];
            A0[0] = *(const float4*)(Qg0 + c * 32);
            A0[1] = *(const float4*)(Qg0 + c * 32 + 16);
            A1[0] = *(const float4*)(Qg1 + c * 32);
            A1[1] = *(const float4*)(Qg1 + c * 32 + 16);
            storeA_h(AFQ + c * AFW1H, A0, A1, wmS, iS, g, tg);
        }
    }

    float m8[8], l8[8], oacc[4][4][4];
#pragma unroll
    for (int s = 0; s < 8; s++) { m8[s] = -1e30f; l8[s] = 0.f; }
#pragma unroll
    for (int i = 0; i < 4; i++)
#pragma unroll
        for (int j = 0; j < 4; j++)
#pragma unroll
            for (int r = 0; r < 4; r++) oacc[i][j][r] = 0.f;

    int q = 0;
    for (int t = 0; t < 16; t++) {
        float sacc[4][4][4];
#pragma unroll
        for (int i = 0; i < 4; i++)
#pragma unroll
            for (int j = 0; j < 4; j++)
#pragma unroll
                for (int r = 0; r < 4; r++) sacc[i][j][r] = 0.f;

        // S = Q @ K tile: 2 chunks x 4 ks-blocks
        for (int c = 0; c < 2; c++, q++) {
            WAITG1();
            __syncthreads();
            if (q + 2 < 64) issue_body(q + 2);
            COMMIT();
            const uint32_t* Bs = BBuf + (q % 3) * FBBW;
#pragma unroll
            for (int ks4 = 0; ks4 < 4; ks4++) {
                const uint32_t* AFr = AFQ + (c * 2 + (ks4 >> 1)) * AFW1H;
                const int ks = ks4 & 1;
                uint32_t af[4][4], bf[4][2];
#pragma unroll
                for (int i = 0; i < 4; i++) {
                    const uint4 qd = *(const uint4*)
                        &AFr[(((wm * 2 + ks) * 4 + i) * 32 + (lane ^ (g & 3))) * 4];
                    af[i][0] = qd.x; af[i][1] = qd.y; af[i][2] = qd.z; af[i][3] = qd.w;
                }
                const int kl = ks4 * 8 + tg;
#pragma unroll
                for (int j = 0; j < 4; j++) {
                    const int c0 = wn * 32 + j * 8 + g;
                    bf[j][0] = Bs[kl * HPITCH + c0];
                    bf[j][1] = Bs[(kl + 4) * HPITCH + c0];
                }
#pragma unroll
                for (int i = 0; i < 4; i++)
#pragma unroll
                    for (int j = 0; j < 4; j++) MMA_F16(sacc[i][j], af[i], bf[j]);
            }
            __syncthreads();
        }

        // scale + bias
#pragma unroll
        for (int i = 0; i < 4; i++) {
            const int rg = by * 128 + wm * 64 + i * 16 + g;
#pragma unroll
            for (int j = 0; j < 4; j++) {
                const int cg = t * 128 + wn * 32 + j * 8 + 2 * tg;
                const float2 b0 = *(const float2*)(bias2d + (size_t)rg * NTOK + cg);
                const float2 b1 = *(const float2*)(bias2d + (size_t)(rg + 8) * NTOK + cg);
                sacc[i][j][0] = sacc[i][j][0] * SCALE + b0.x;
                sacc[i][j][1] = sacc[i][j][1] * SCALE + b0.y;
                sacc[i][j][2] = sacc[i][j][2] * SCALE + b1.x;
                sacc[i][j][3] = sacc[i][j][3] * SCALE + b1.y;
            }
        }

        // online softmax
        float pm[8];
#pragma unroll
        for (int i = 0; i < 4; i++)
#pragma unroll
            for (int h2i = 0; h2i < 2; h2i++) {
                float v = -1e30f;
#pragma unroll
                for (int j = 0; j < 4; j++)
                    v = fmaxf(v, fmaxf(sacc[i][j][2 * h2i], sacc[i][j][2 * h2i + 1]));
                pm[i * 2 + h2i] = v;
            }
#pragma unroll
        for (int s = 0; s < 8; s++) {
            pm[s] = fmaxf(pm[s], __shfl_xor_sync(~0u, pm[s], 1));
            pm[s] = fmaxf(pm[s], __shfl_xor_sync(~0u, pm[s], 2));
        }
#pragma unroll
        for (int s = 0; s < 8; s++) {
            const int row = wm * 64 + (s >> 1) * 16 + (s & 1) * 8 + g;
            if (tg == 0) redM[row * 4 + wn] = pm[s];
        }
        __syncthreads();

        float alpha[8], nm[8];
#pragma unroll
        for (int s = 0; s < 8; s++) {
            const int row = wm * 64 + (s >> 1) * 16 + (s & 1) * 8 + g;
            float tm = fmaxf(fmaxf(redM[row * 4], redM[row * 4 + 1]),
                             fmaxf(redM[row * 4 + 2], redM[row * 4 + 3]));
            nm[s] = fmaxf(m8[s], tm);
            alpha[s] = __expf(m8[s] - nm[s]);
            m8[s] = nm[s];
        }

        float ps[8];
#pragma unroll
        for (int s = 0; s < 8; s++) ps[s] = 0.f;
#pragma unroll
        for (int i = 0; i < 4; i++)
#pragma unroll
            for (int h2i = 0; h2i < 2; h2i++) {
                const int row = wm * 64 + i * 16 + h2i * 8 + g;
#pragma unroll
                for (int j = 0; j < 4; j++) {
                    const int cw = wn * 16 + j * 4 + tg;
                    float p0 = __expf(sacc[i][j][2 * h2i] - nm[i * 2 + h2i]);
                    float p1 = __expf(sacc[i][j][2 * h2i + 1] - nm[i * 2 + h2i]);
                    ps[i * 2 + h2i] += p0 + p1;
                    Ps[row * PSP + cw] = h2(p0, p1);
                }
            }
#pragma unroll
        for (int s = 0; s < 8; s++) {
            ps[s] += __shfl_xor_sync(~0u, ps[s], 1);
            ps[s] += __shfl_xor_sync(~0u, ps[s], 2);
            const int row = wm * 64 + (s >> 1) * 16 + (s & 1) * 8 + g;
            if (tg == 0) redS[row * 4 + wn] = ps[s];
        }
        __syncthreads();
#pragma unroll
        for (int s = 0; s < 8; s++) {
            const int row = wm * 64 + (s >> 1) * 16 + (s & 1) * 8 + g;
            const float ts = redS[row * 4] + redS[row * 4 + 1] +
                             redS[row * 4 + 2] + redS[row * 4 + 3];
            l8[s] = alpha[s] * l8[s] + ts;
        }
#pragma unroll
        for (int i = 0; i < 4; i++)
#pragma unroll
            for (int j = 0; j < 4; j++) {
                oacc[i][j][0] *= alpha[i * 2];
                oacc[i][j][1] *= alpha[i * 2];
                oacc[i][j][2] *= alpha[i * 2 + 1];
                oacc[i][j][3] *= alpha[i * 2 + 1];
            }

        // O += P @ V tile: 2 chunks x 4 ks-blocks
        for (int c = 0; c < 2; c++, q++) {
            WAITG1();
            __syncthreads();
            if (q + 2 < 64) issue_body(q + 2);
            COMMIT();
            const uint32_t* Bs = BBuf + (q % 3) * FBBW;
#pragma unroll
            for (int ks4 = 0; ks4 < 4; ks4++) {
                uint32_t af[4][4], bf[4][2];
                const int kk = c * 32 + ks4 * 8 + tg;
#pragma unroll
                for (int i = 0; i < 4; i++) {
                    const int r0 = wm * 64 + i * 16 + g;
                    af[i][0] = Ps[r0 * PSP + kk];
                    af[i][1] = Ps[(r0 + 8) * PSP + kk];
                    af[i][2] = Ps[r0 * PSP + kk + 4];
                    af[i][3] = Ps[(r0 + 8) * PSP + kk + 4];
                }
                const int kl = ks4 * 8 + tg;
#pragma unroll
                for (int j = 0; j < 4; j++) {
                    const int c0 = wn * 32 + j * 8 + g;
                    bf[j][0] = Bs[kl * HPITCH + c0];
                    bf[j][1] = Bs[(kl + 4) * HPITCH + c0];
                }
#pragma unroll
                for (int i = 0; i < 4; i++)
#pragma unroll
                    for (int j = 0; j < 4; j++) MMA_F16(oacc[i][j], af[i], bf[j]);
            }
            __syncthreads();
        }
    }

    float* Oh = O + (size_t)h * 256 * DMOD;
#pragma unroll
    for (int i = 0; i < 4; i++) {
        const int row = by * 128 + wm * 64 + i * 16 + g;
        const float inv0 = 1.f / l8[i * 2];
        const float inv1 = 1.f / l8[i * 2 + 1];
#pragma unroll
        for (int j = 0; j < 4; j++) {
            const int col = wn * 32 + j * 8 + 2 * tg;
            *(float2*)(Oh + (size_t)row * DKH + col) =
                make_float2(oacc[i][j][0] * inv0, oacc[i][j][1] * inv0);
            *(float2*)(Oh + (size_t)(row + 8) * DKH + col) =
                make_float2(oacc[i][j][2] * inv1, oacc[i][j][3] * inv1);
        }
    }
}

// ---- weight pack ----
__global__ void packW_k(const float* __restrict__ W, uint32_t* __restrict__ Wp, int N)
{
    const size_t i = (size_t)blockIdx.x * 256 + threadIdx.x;
    const size_t k2 = i / N, n = i - k2 * N;
    Wp[i] = h2(W[2 * k2 * N + n], W[(2 * k2 + 1) * N + n]);
}

// ---- K/V repack ----
__global__ void packKV_k(const float* __restrict__ qkv,
                         uint32_t* __restrict__ Kp, uint32_t* __restrict__ Vp)
{
    const size_t i = (size_t)blockIdx.x * 256 + threadIdx.x;
    const size_t ND = (size_t)NTOK * DMOD;
    if (blockIdx.z == 0) {
        const int hh = (int)(i >> 17);
        const size_t r = i & 131071;
        const size_t d2 = r >> 11, tk = r & 2047;
        const float* base = qkv + ND + (size_t)hh * 256 * DMOD;
        Kp[i] = h2(base[2 * d2 * 2048 + tk], base[(2 * d2 + 1) * 2048 + tk]);
    } else {
        const int hh = (int)(i >> 17);
        const size_t r = i & 131071;
        const size_t t2 = r >> 7, d = r & 127;
        const float* base = qkv + 2 * ND + (size_t)hh * 256 * DMOD;
        Vp[i] = h2(base[2 * t2 * 128 + d], base[(2 * t2 + 1) * 128 + d]);
    }
}

// ---- split-K reduce (QKV path) ----
__global__ void reduceK_k(const float4* __restrict__ part, float4* __restrict__ outp,
                          const float* __restrict__ bias, int nsplit, size_t MN4,
                          int N4, int sB4)
{
    const size_t i = (size_t)blockIdx.x * blockDim.x + threadIdx.x;
    const size_t b = i / MN4, e = i - b * MN4;
    const float4* p = part + b * (size_t)nsplit * MN4 + e;
    float4 a = p[0];
    for (int s = 1; s < nsplit; s++) {
        const float4 v = p[(size_t)s * MN4];
        a.x += v.x; a.y += v.y; a.z += v.z; a.w += v.w;
    }
    if (bias) {
        const float4 bb = ((const float4*)bias)[b * sB4 + (e % N4)];
        a.x += bb.x; a.y += bb.y; a.z += bb.z; a.w += bb.w;
    }
    outp[i] = a;
}

// ---- fused: y = LayerNorm(resid + part0 + part1 + bias) * g + b ----
__global__ void red_ln_k(const float* __restrict__ part,
                         const float* __restrict__ bias,
                         const float* __restrict__ resid,
                         const float* __restrict__ g, const float* __restrict__ b,
                         float* __restrict__ y)
{
    const int n = blockIdx.x;
    const size_t ND = (size_t)NTOK * DMOD;
    const float4* p0 = (const float4*)(part + (size_t)n * DMOD);
    const float4* p1 = (const float4*)(part + ND + (size_t)n * DMOD);
    const float4* br = (const float4*)bias;
    const float4* rr = (const float4*)(resid + (size_t)n * DMOD);
    const int i = threadIdx.x;  // 256 threads x float4 = 1024
    float4 a = p0[i], c = p1[i], bb = br[i], r = rr[i];
    float v0 = r.x + a.x + c.x + bb.x;
    float v1 = r.y + a.y + c.y + bb.y;
    float v2 = r.z + a.z + c.z + bb.z;
    float v3 = r.w + a.w + c.w + bb.w;

    __shared__ float r1[256], r2[256];
    r1[i] = v0 + v1 + v2 + v3;
    r2[i] = v0 * v0 + v1 * v1 + v2 * v2 + v3 * v3;
    __syncthreads();
    for (int st = 128; st > 0; st >>= 1) {
        if (i < st) { r1[i] += r1[i + st]; r2[i] += r2[i + st]; }
        __syncthreads();
    }
    const float mean = r1[0] * (1.f / DMOD);
    const float var = r2[0] * (1.f / DMOD) - mean * mean;
    const float rstd = rsqrtf(var + 1e-5f);
    const float4 gg = ((const float4*)g)[i];
    const float4 b2v = ((const float4*)b)[i];
    float4 o;
    o.x = (v0 - mean) * rstd * gg.x + b2v.x;
    o.y = (v1 - mean) * rstd * gg.y + b2v.y;
    o.z = (v2 - mean) * rstd * gg.z + b2v.z;
    o.w = (v3 - mean) * rstd * gg.w + b2v.w;
    ((float4*)(y + (size_t)n * DMOD))[i] = o;
}

__global__ void addemb_k(const float* __restrict__ x, const int* __restrict__ ind,
                         const int* __restrict__ outd, const float* __restrict__ ie,
                         const float* __restrict__ oe, float* __restrict__ x2)
{
    const int n = blockIdx.x;
    const float4* xr = (const float4*)(x + (size_t)n * DMOD);
    const float4* ir = (const float4*)(ie + (size_t)ind[n] * DMOD);
    const float4* orr = (const float4*)(oe + (size_t)outd[n] * DMOD);
    const int i = threadIdx.x;
    float4 a = xr[i], b = ir[i], c = orr[i];
    a.x += b.x + c.x; a.y += b.y + c.y; a.z += b.z + c.z; a.w += b.w + c.w;
    ((float4*)(x2 + (size_t)n * DMOD))[i] = a;
}

__global__ void etw_k(const float* __restrict__ re, const float* __restrict__ rw,
                      float* __restrict__ etw)
{
    const int t = threadIdx.x;
    float s = 0.f;
    for (int j = 0; j < DKH; j++) s += re[t * DKH + j] * rw[t * DKH + j];
    etw[t] = s * SCALE;
}

__global__ void bias2d_k(const int* __restrict__ dist, const int4* __restrict__ pet,
                         const float4* __restrict__ paw, const float* __restrict__ plen,
                         const float* __restrict__ etw, float* __restrict__ out)
{
    const size_t i = (size_t)blockIdx.x * blockDim.x + threadIdx.x;
    const int4 e = pet[i];
    const float4 w = paw[i];
    float b = plen[dist[i]];
    b += etw[e.x] * w.x + etw[e.y] * w.y + etw[e.z] * w.z + etw[e.w] * w.w;
    out[i] = b;
}

// ---------------------------------------------------------------------------
extern "C" void kernel_launch(void* const* d_in, const int* in_sizes, int n_in,
                              void* d_out, int out_size)
{
    const float* x      = (const float*)d_in[0];
    const float* lgx    = (const float*)d_in[1];
    const int* in_deg   = (const int*)d_in[2];
    const int* out_deg  = (const int*)d_in[3];
    const int* dist     = (const int*)d_in[4];
    const int* pet      = (const int*)d_in[5];
    const float* paw    = (const float*)d_in[6];
    const float* rel_e  = (const float*)d_in[7];
    const float* rel_w  = (const float*)d_in[8];
    const float* ide    = (const float*)d_in[9];
    const float* ode    = (const float*)d_in[10];
    const float* plen   = (const float*)d_in[11];
    const float* Wq = (const float*)d_in[12];  const float* bq = (const float*)d_in[13];
    const float* Wk = (const float*)d_in[14];  const float* bk = (const float*)d_in[15];
    const float* Wv = (const float*)d_in[16];  const float* bv = (const float*)d_in[17];
    const float* Wo = (const float*)d_in[18];  const float* bo = (const float*)d_in[19];
    const float* ln1g = (const float*)d_in[20]; const float* ln1b = (const float*)d_in[21];
    const float* W1 = (const float*)d_in[22];  const float* b1 = (const float*)d_in[23];
    const float* W2 = (const float*)d_in[24];  const float* b2 = (const float*)d_in[25];
    const float* ln2g = (const float*)d_in[26]; const float* ln2b = (const float*)d_in[27];
    float* out = (float*)d_out;

    float *x2, *bias2d, *bqkv, *qkv, *ao, *h1, *ff, *part, *etw;
    uint32_t *Wqp, *Wop, *W1p, *W2p, *Kp, *Vp;
    cudaGetSymbolAddress((void**)&x2, g_x2);
    cudaGetSymbolAddress((void**)&bias2d, g_bias2d);
    cudaGetSymbolAddress((void**)&bqkv, g_bqkv);
    cudaGetSymbolAddress((void**)&qkv, g_qkv);
    cudaGetSymbolAddress((void**)&ao, g_ao);
    cudaGetSymbolAddress((void**)&h1, g_h1);
    cudaGetSymbolAddress((void**)&ff, g_ff);
    cudaGetSymbolAddress((void**)&part, g_part);
    cudaGetSymbolAddress((void**)&etw, g_etw);
    cudaGetSymbolAddress((void**)&Wqp, g_Wqp);
    cudaGetSymbolAddress((void**)&Wop, g_Wop);
    cudaGetSymbolAddress((void**)&W1p, g_W1p);
    cudaGetSymbolAddress((void**)&W2p, g_W2p);
    cudaGetSymbolAddress((void**)&Kp, g_Kp);
    cudaGetSymbolAddress((void**)&Vp, g_Vp);

    cudaFuncSetAttribute(hgemm, cudaFuncAttributeMaxDynamicSharedMemorySize,
                         HSMEM_BYTES);
    cudaFuncSetAttribute(flash_h, cudaFuncAttributeMaxDynamicSharedMemorySize,
                         FLASH_SMEM);

    static cudaStream_t s2 = nullptr;
    static cudaEvent_t evFork = nullptr, evJoin = nullptr;
    if (!s2) {
        cudaStreamCreateWithFlags(&s2, cudaStreamNonBlocking);
        cudaEventCreateWithFlags(&evFork, cudaEventDisableTiming);
        cudaEventCreateWithFlags(&evJoin, cudaEventDisableTiming);
    }

    const size_t ND = (size_t)NTOK * DMOD;

    // fork: lgx copy + etw + bias2d on side stream
    cudaEventRecord(evFork, 0);
    cudaStreamWaitEvent(s2, evFork, 0);
    cudaMemcpyAsync(out + ND, lgx, (size_t)NTOK * 8 * DMOD * sizeof(float),
                    cudaMemcpyDeviceToDevice, s2);
    etw_k<<<1, 64, 0, s2>>>(rel_e, rel_w, etw);
    bias2d_k<<<(NTOK * NTOK) / 256, 256, 0, s2>>>(
        dist, (const int4*)pet, (const float4*)paw, plen, etw, bias2d);
    cudaEventRecord(evJoin, s2);

    // main: pack weights, biases, addemb
    const int WQW = 512 * DMOD;
    packW_k<<<WQW / 256, 256>>>(Wq, Wqp, DMOD);
    packW_k<<<WQW / 256, 256>>>(Wk, Wqp + WQW, DMOD);
    packW_k<<<WQW / 256, 256>>>(Wv, Wqp + 2 * WQW, DMOD);
    packW_k<<<WQW / 256, 256>>>(Wo, Wop, DMOD);
    packW_k<<<512 * FFD / 256, 256>>>(W1, W1p, FFD);
    packW_k<<<2048 * DMOD / 256, 256>>>(W2, W2p, DMOD);
    cudaMemcpyAsync(bqkv,            bq, DMOD * 4, cudaMemcpyDeviceToDevice);
    cudaMemcpyAsync(bqkv + DMOD,     bk, DMOD * 4, cudaMemcpyDeviceToDevice);
    cudaMemcpyAsync(bqkv + 2 * DMOD, bv, DMOD * 4, cudaMemcpyDeviceToDevice);
    addemb_k<<<NTOK, 256>>>(x, in_deg, out_deg, ide, ode, x2);

    // QKV: split-K=2, 3 batches -> partials, reduce(+bqkv)
    hgemm<<<dim3(8, 16, 6), 256, HSMEM_BYTES>>>(
        x2, Wqp, nullptr, part, NTOK, DMOD, DMOD,
        0, (size_t)WQW, ND, 0, 0, 2);
    reduceK_k<<<(int)(3 * ND / 4 / 256), 256>>>(
        (const float4*)part, (float4*)qkv, bqkv, 2, ND / 4, DMOD / 4, DMOD / 4);

    // repack K,V to half2
    packKV_k<<<dim3(HEADS * 64 * NTOK / 256, 1, 2), 256>>>(qkv, Kp, Vp);

    // join: flash needs bias2d
    cudaStreamWaitEvent(0, evJoin, 0);
    flash_h<<<dim3(1, 16, HEADS), 256, FLASH_SMEM>>>(qkv, Kp, Vp, bias2d, ao);

    // Wo: split-K=2 -> partials; fused reduce+bo+residual(x2)+LN1 -> h1
    hgemm<<<dim3(8, 16, 2), 256, HSMEM_BYTES>>>(
        ao, Wop, nullptr, part, NTOK, DMOD, DMOD, 0, 0, ND, 0, 0, 2);
    red_ln_k<<<NTOK, 256>>>(part, bo, x2, ln1g, ln1b, h1);

    // FFN1 (+b1, relu)
    hgemm<<<dim3(32, 16, 1), 256, HSMEM_BYTES>>>(
        h1, W1p, b1, ff, NTOK, FFD, DMOD, 0, 0, 0, FFD, 1, 1);
    // FFN2: split-K=2 -> partials; fused reduce+b2+residual(h1)+LN2 -> out
    hgemm<<<dim3(8, 16, 2), 256, HSMEM_BYTES>>>(
        ff, W2p, nullptr, part, NTOK, DMOD, FFD, 0, 0, ND, 0, 0, 2);
    red_ln_k<<<NTOK, 256>>>(part, b2, h1, ln2g, ln2b, out);
}

// round 13
// speedup vs baseline: 1.4855x; 1.0333x over previous
#include <cuda_runtime.h>
#include <cuda_fp16.h>
#include <cstdint>
#include <cstddef>

// ---------------------------------------------------------------------------
// Rel_Transformer_Layer: N=2048, D=1024, H=8, DK=128, L=4, FF=4096
// Round 13: fp16 pipeline (R12) + 64-row flash blocks (occ 2, 256 blocks,
// stalls overlap across co-resident CTAs) + weight packs on side stream.
// ---------------------------------------------------------------------------

#define NTOK 2048
#define DMOD 1024
#define HEADS 8
#define DKH 128
#define FFD 4096
#define SCALE 0.08838834764831845f

// -------------------- scratch ------------------
__device__ float g_x2[NTOK * DMOD];
__device__ float g_bias2d[(size_t)NTOK * NTOK];
__device__ float g_bqkv[3 * DMOD];
__device__ float g_qkv[3 * NTOK * DMOD];
__device__ float g_ao[NTOK * DMOD];
__device__ float g_h1[NTOK * DMOD];
__device__ float g_ff[(size_t)NTOK * FFD];
__device__ float g_part[(size_t)6 * NTOK * DMOD];
__device__ float g_etw[64];
__device__ uint32_t g_Wqp[3 * 512 * DMOD];
__device__ uint32_t g_Wop[512 * DMOD];
__device__ uint32_t g_W1p[512 * FFD];
__device__ uint32_t g_W2p[2048 * DMOD];
__device__ uint32_t g_Kp[HEADS * 64 * NTOK];   // [h][dk/2][tok]
__device__ uint32_t g_Vp[HEADS * 1024 * DKH];  // [h][tok/2][dk]

// -------------------- helpers ------------------
__device__ __forceinline__ uint32_t h2(float a, float b) {
    __half2 h = __floats2half2_rn(a, b);
    return *(uint32_t*)&h;
}
__device__ __forceinline__ void cpasync16(uint32_t s, const void* g) {
    asm volatile("cp.async.cg.shared.global [%0], [%1], 16;" :: "r"(s), "l"(g));
}
#define COMMIT() asm volatile("cp.async.commit_group;" ::: "memory")
#define WAITG1() asm volatile("cp.async.wait_group 1;" ::: "memory")

#define MMA_F16(acc, af, bf)                                               \
    asm volatile(                                                          \
        "mma.sync.aligned.m16n8k16.row.col.f32.f16.f16.f32 "               \
        "{%0,%1,%2,%3}, {%4,%5,%6,%7}, {%8,%9}, {%0,%1,%2,%3};"            \
        : "+f"(acc[0]), "+f"(acc[1]), "+f"(acc[2]), "+f"(acc[3])           \
        : "r"(af[0]), "r"(af[1]), "r"(af[2]), "r"(af[3]),                  \
          "r"(bf[0]), "r"(bf[1]))

#define AFW1H 2048
__device__ __forceinline__ void storeA_h(
    uint32_t* AFb, const float4 A0[2], const float4 A1[2],
    int wmS, int iS, int g, int tg)
{
#pragma unroll
    for (int ks = 0; ks < 2; ks++) {
        const float* f0 = (const float*)&A0[ks];
        const float* f1 = (const float*)&A1[ks];
#pragma unroll
        for (int pp = 0; pp < 2; pp++) {
            const int kp = 2 * tg + pp;
            const int tgp = kp & 3;
            const int hk = kp >> 2;
            const uint32_t w0 = h2(f0[2 * pp], f0[2 * pp + 1]);
            const uint32_t w1 = h2(f1[2 * pp], f1[2 * pp + 1]);
            const int idx = (((wmS * 2 + ks) * 4 + iS) * 32 +
                             ((g * 4 + tgp) ^ (g & 3))) * 4 + 2 * hk;
            *(uint2*)&AFb[idx] = make_uint2(w0, w1);
        }
    }
}

// 64-row variant: 8 fragment blocks (wm2 x ks2 x i2), producer warp owns 8
// rows; parity selects the row-r (words 0,2) vs row-r+8 (words 1,3) slots.
__device__ __forceinline__ void storeA_h64(
    uint32_t* AFb, const float4 A0, const float4 A1,
    int wmS, int iS, int par, int g, int tg)
{
    const float4 A[2] = {A0, A1};
#pragma unroll
    for (int ks = 0; ks < 2; ks++) {
        const float* f = (const float*)&A[ks];
#pragma unroll
        for (int pp = 0; pp < 2; pp++) {
            const int kp = 2 * tg + pp;
            const int tgp = kp & 3;
            const int hk = kp >> 2;
            const uint32_t w = h2(f[2 * pp], f[2 * pp + 1]);
            const int idx = (((wmS * 2 + ks) * 2 + iS) * 32 +
                             ((g * 4 + tgp) ^ (g & 3))) * 4 + 2 * hk + par;
            AFb[idx] = w;
        }
    }
}

// ==================== fp16 GEMM (round-11 verified) ====================
#define HPITCH 136
#define HBBW (16 * HPITCH)
#define HSMEM_BYTES ((2 * AFW1H + 3 * HBBW) * 4)

__global__ __launch_bounds__(256, 2) void hgemm(
    const float* __restrict__ A, const uint32_t* __restrict__ Bp,
    const float* __restrict__ biasvec, float* __restrict__ C,
    int M, int N, int K, size_t sA, size_t sBp, size_t sC, size_t sBias,
    int doRelu, int nsplit)
{
    extern __shared__ uint32_t sm[];
    uint32_t* AF = sm;
    uint32_t* BBuf = sm + 2 * AFW1H;

    const int tid = threadIdx.x, wid = tid >> 5, lane = tid & 31;
    const int g = lane >> 2, tg = lane & 3, wm = wid >> 2, wn = wid & 3;
    const int batch = blockIdx.z / nsplit, split = blockIdx.z - batch * nsplit;
    const int Keff = K / nsplit, nIter = Keff / 32;

    const float* Ab = A + (size_t)batch * sA + (size_t)split * Keff
                        + (size_t)blockIdx.y * 128 * K;
    const uint32_t* Bb = Bp + (size_t)batch * sBp
                        + (size_t)(split * Keff / 2) * N + (size_t)blockIdx.x * 128;
    float* Cb = C + (size_t)blockIdx.z * sC;
    const float* bvv = biasvec ? biasvec + (size_t)batch * sBias : nullptr;

    const int wmS = wid >> 2, iS = wid & 3;
    const float* Ag0 = Ab + (size_t)(wid * 16 + g) * K + tg * 4;
    const float* Ag1 = Ag0 + (size_t)8 * K;

    const int bRow = tid >> 5;
    const int bCol = (tid & 31) << 2;
    const uint32_t* Bg = Bb + (size_t)bRow * N + bCol;
    const uint32_t bSh = (uint32_t)__cvta_generic_to_shared(BBuf);

    float4 A0[2], A1[2];
    A0[0] = *(const float4*)(Ag0);       A0[1] = *(const float4*)(Ag0 + 16);
    A1[0] = *(const float4*)(Ag1);       A1[1] = *(const float4*)(Ag1 + 16);
    storeA_h(AF, A0, A1, wmS, iS, g, tg);
#pragma unroll
    for (int rh = 0; rh < 16; rh += 8)
        cpasync16(bSh + (((bRow + rh) * HPITCH + bCol) << 2), Bg + (size_t)rh * N);
    COMMIT();
    A0[0] = *(const float4*)(Ag0 + 32);  A0[1] = *(const float4*)(Ag0 + 48);
    A1[0] = *(const float4*)(Ag1 + 32);  A1[1] = *(const float4*)(Ag1 + 48);
    {
        const uint32_t* Bn = Bg + (size_t)16 * N;
        const uint32_t db = bSh + (HBBW << 2);
#pragma unroll
        for (int rh = 0; rh < 16; rh += 8)
            cpasync16(db + (((bRow + rh) * HPITCH + bCol) << 2), Bn + (size_t)rh * N);
    }
    COMMIT();

    float acc[4][4][4];
#pragma unroll
    for (int i = 0; i < 4; i++)
#pragma unroll
        for (int j = 0; j < 4; j++)
#pragma unroll
            for (int r = 0; r < 4; r++) acc[i][j][r] = 0.f;

    for (int it = 0; it < nIter; it++) {
        WAITG1();
        __syncthreads();
        if (it + 2 < nIter) {
            const uint32_t* Bn = Bg + (size_t)(it + 2) * 16 * N;
            const uint32_t db = bSh + (((it + 2) % 3) * HBBW << 2);
#pragma unroll
            for (int rh = 0; rh < 16; rh += 8)
                cpasync16(db + (((bRow + rh) * HPITCH + bCol) << 2), Bn + (size_t)rh * N);
        }
        COMMIT();
        if (it + 1 < nIter)
            storeA_h(AF + ((it + 1) & 1) * AFW1H, A0, A1, wmS, iS, g, tg);
        if (it + 2 < nIter) {
            const float* An0 = Ag0 + (size_t)(it + 2) * 32;
            const float* An1 = Ag1 + (size_t)(it + 2) * 32;
            A0[0] = *(const float4*)(An0);  A0[1] = *(const float4*)(An0 + 16);
            A1[0] = *(const float4*)(An1);  A1[1] = *(const float4*)(An1 + 16);
        }
        const uint32_t* AFr = AF + (it & 1) * AFW1H;
        const uint32_t* Bs = BBuf + (it % 3) * HBBW;
#pragma unroll
        for (int ks = 0; ks < 2; ks++) {
            uint32_t af[4][4], bf[4][2];
#pragma unroll
            for (int i = 0; i < 4; i++) {
                const uint4 qd = *(const uint4*)
                    &AFr[(((wm * 2 + ks) * 4 + i) * 32 + (lane ^ (g & 3))) * 4];
                af[i][0] = qd.x; af[i][1] = qd.y; af[i][2] = qd.z; af[i][3] = qd.w;
            }
            const int kl = ks * 8 + tg;
#pragma unroll
            for (int j = 0; j < 4; j++) {
                const int c0 = wn * 32 + j * 8 + g;
                bf[j][0] = Bs[kl * HPITCH + c0];
                bf[j][1] = Bs[(kl + 4) * HPITCH + c0];
            }
#pragma unroll
            for (int i = 0; i < 4; i++)
#pragma unroll
                for (int j = 0; j < 4; j++) MMA_F16(acc[i][j], af[i], bf[j]);
        }
        __syncthreads();
    }

#pragma unroll
    for (int i = 0; i < 4; i++) {
        const int row = blockIdx.y * 128 + wm * 64 + i * 16 + g;
#pragma unroll
        for (int j = 0; j < 4; j++) {
            const int col = blockIdx.x * 128 + wn * 32 + j * 8 + 2 * tg;
            float v0 = acc[i][j][0], v1 = acc[i][j][1];
            float v2 = acc[i][j][2], v3 = acc[i][j][3];
            if (bvv) {
                v0 += bvv[col]; v1 += bvv[col + 1];
                v2 += bvv[col]; v3 += bvv[col + 1];
            }
            if (doRelu) {
                v0 = fmaxf(v0, 0.f); v1 = fmaxf(v1, 0.f);
                v2 = fmaxf(v2, 0.f); v3 = fmaxf(v3, 0.f);
            }
            *(float2*)(Cb + (size_t)row * N + col) = make_float2(v0, v1);
            *(float2*)(Cb + (size_t)(row + 8) * N + col) = make_float2(v2, v3);
        }
    }
}

// ==================== fp16 flash, 64-row blocks, occ 2 ====================
// smem words: AFQ[4096] | BBuf[3*4352] | Ps[64*68] | redM[256] redS[256]
#define FBBW (32 * HPITCH)                 // 4352
#define PSP 68
#define F6_BB  4096
#define F6_PS  (F6_BB + 3 * FBBW)          // 17152
#define F6_RED (F6_PS + 64 * PSP)          // 21504
#define FLASH_SMEM ((F6_RED + 512) * 4)    // 88064

__global__ __launch_bounds__(256, 2) void flash_h(
    const float* __restrict__ Q, const uint32_t* __restrict__ Kp,
    const uint32_t* __restrict__ Vp, const float* __restrict__ bias2d,
    float* __restrict__ O)
{
    extern __shared__ uint32_t sm[];
    uint32_t* AFQ = sm;
    uint32_t* BBuf = sm + F6_BB;
    uint32_t* Ps = sm + F6_PS;
    float* redM = (float*)(sm + F6_RED);
    float* redS = redM + 256;

    const int tid = threadIdx.x, wid = tid >> 5, lane = tid & 31;
    const int g = lane >> 2, tg = lane & 3, wm = wid >> 2, wn = wid & 3;
    const int h = blockIdx.z, by = blockIdx.y;  // by 0..31, 64 rows each

    const float* Qh = Q + (size_t)h * 256 * DMOD;
    const uint32_t* Kh = Kp + (size_t)h * 64 * NTOK;
    const uint32_t* Vh = Vp + (size_t)h * 1024 * DKH;

    const int bRow = tid >> 5, bCol = (tid & 31) << 2;
    const uint32_t bSh = (uint32_t)__cvta_generic_to_shared(BBuf);
    auto issue_body = [&](int qq) {
        const int t = qq >> 2, ph = qq & 3;
        const uint32_t* src;
        int stride;
        if (ph < 2) { src = Kh + (size_t)(ph * 32 + bRow) * NTOK + t * 128 + bCol; stride = NTOK; }
        else        { src = Vh + (size_t)(t * 64 + (ph - 2) * 32 + bRow) * DKH + bCol; stride = DKH; }
        const uint32_t db = bSh + ((qq % 3) * FBBW << 2);
#pragma unroll
        for (int rh = 0; rh < 32; rh += 8)
            cpasync16(db + (((bRow + rh) * HPITCH + bCol) << 2), src + (size_t)rh * stride);
    };
    issue_body(0); COMMIT();
    issue_body(1); COMMIT();

    // Q staging: warp wid owns rows by*64 + wid*8 + g
    {
        const int blk = wid >> 1, par = wid & 1;
        const int wmS = blk >> 1, iS = blk & 1;
        const float* Qg = Qh + (size_t)(by * 64 + wid * 8 + g) * DKH + tg * 4;
#pragma unroll
        for (int c = 0; c < 4; c++) {
            const float4 A0 = *(const float4*)(Qg + c * 32);
            const float4 A1 = *(const float4*)(Qg + c * 32 + 16);
            storeA_h64(AFQ + c * 1024, A0, A1, wmS, iS, par, g, tg);
        }
    }

    float m4[4], l4[4], oacc[2][4][4];
#pragma unroll
    for (int s = 0; s < 4; s++) { m4[s] = -1e30f; l4[s] = 0.f; }
#pragma unroll
    for (int i = 0; i < 2; i++)
#pragma unroll
        for (int j = 0; j < 4; j++)
#pragma unroll
            for (int r = 0; r < 4; r++) oacc[i][j][r] = 0.f;

    int q = 0;
    for (int t = 0; t < 16; t++) {
        float sacc[2][4][4];
#pragma unroll
        for (int i = 0; i < 2; i++)
#pragma unroll
            for (int j = 0; j < 4; j++)
#pragma unroll
                for (int r = 0; r < 4; r++) sacc[i][j][r] = 0.f;

        // S = Q @ K tile: 2 chunks x 4 ks-blocks
        for (int c = 0; c < 2; c++, q++) {
            WAITG1();
            __syncthreads();
            if (q + 2 < 64) issue_body(q + 2);
            COMMIT();
            const uint32_t* Bs = BBuf + (q % 3) * FBBW;
#pragma unroll
            for (int ks4 = 0; ks4 < 4; ks4++) {
                const uint32_t* AFr = AFQ + (c * 2 + (ks4 >> 1)) * 1024;
                const int ks = ks4 & 1;
                uint32_t af[2][4], bf[4][2];
#pragma unroll
                for (int i = 0; i < 2; i++) {
                    const uint4 qd = *(const uint4*)
                        &AFr[(((wm * 2 + ks) * 2 + i) * 32 + (lane ^ (g & 3))) * 4];
                    af[i][0] = qd.x; af[i][1] = qd.y; af[i][2] = qd.z; af[i][3] = qd.w;
                }
                const int kl = ks4 * 8 + tg;
#pragma unroll
                for (int j = 0; j < 4; j++) {
                    const int c0 = wn * 32 + j * 8 + g;
                    bf[j][0] = Bs[kl * HPITCH + c0];
                    bf[j][1] = Bs[(kl + 4) * HPITCH + c0];
                }
#pragma unroll
                for (int i = 0; i < 2; i++)
#pragma unroll
                    for (int j = 0; j < 4; j++) MMA_F16(sacc[i][j], af[i], bf[j]);
            }
            __syncthreads();
        }

        // scale + bias
#pragma unroll
        for (int i = 0; i < 2; i++) {
            const int rg = by * 64 + wm * 32 + i * 16 + g;
#pragma unroll
            for (int j = 0; j < 4; j++) {
                const int cg = t * 128 + wn * 32 + j * 8 + 2 * tg;
                const float2 b0 = *(const float2*)(bias2d + (size_t)rg * NTOK + cg);
                const float2 b1 = *(const float2*)(bias2d + (size_t)(rg + 8) * NTOK + cg);
                sacc[i][j][0] = sacc[i][j][0] * SCALE + b0.x;
                sacc[i][j][1] = sacc[i][j][1] * SCALE + b0.y;
                sacc[i][j][2] = sacc[i][j][2] * SCALE + b1.x;
                sacc[i][j][3] = sacc[i][j][3] * SCALE + b1.y;
            }
        }

        // online softmax (4 row-slots per thread)
        float pm[4];
#pragma unroll
        for (int i = 0; i < 2; i++)
#pragma unroll
            for (int h2i = 0; h2i < 2; h2i++) {
                float v = -1e30f;
#pragma unroll
                for (int j = 0; j < 4; j++)
                    v = fmaxf(v, fmaxf(sacc[i][j][2 * h2i], sacc[i][j][2 * h2i + 1]));
                pm[i * 2 + h2i] = v;
            }
#pragma unroll
        for (int s = 0; s < 4; s++) {
            pm[s] = fmaxf(pm[s], __shfl_xor_sync(~0u, pm[s], 1));
            pm[s] = fmaxf(pm[s], __shfl_xor_sync(~0u, pm[s], 2));
        }
#pragma unroll
        for (int s = 0; s < 4; s++) {
            const int row = wm * 32 + (s >> 1) * 16 + (s & 1) * 8 + g;
            if (tg == 0) redM[row * 4 + wn] = pm[s];
        }
        __syncthreads();

        float alpha[4], nm[4];
#pragma unroll
        for (int s = 0; s < 4; s++) {
            const int row = wm * 32 + (s >> 1) * 16 + (s & 1) * 8 + g;
            float tm = fmaxf(fmaxf(redM[row * 4], redM[row * 4 + 1]),
                             fmaxf(redM[row * 4 + 2], redM[row * 4 + 3]));
            nm[s] = fmaxf(m4[s], tm);
            alpha[s] = __expf(m4[s] - nm[s]);
            m4[s] = nm[s];
        }

        float ps[4];
#pragma unroll
        for (int s = 0; s < 4; s++) ps[s] = 0.f;
#pragma unroll
        for (int i = 0; i < 2; i++)
#pragma unroll
            for (int h2i = 0; h2i < 2; h2i++) {
                const int row = wm * 32 + i * 16 + h2i * 8 + g;
#pragma unroll
                for (int j = 0; j < 4; j++) {
                    const int cw = wn * 16 + j * 4 + tg;
                    float p0 = __expf(sacc[i][j][2 * h2i] - nm[i * 2 + h2i]);
                    float p1 = __expf(sacc[i][j][2 * h2i + 1] - nm[i * 2 + h2i]);
                    ps[i * 2 + h2i] += p0 + p1;
                    Ps[row * PSP + cw] = h2(p0, p1);
                }
            }
#pragma unroll
        for (int s = 0; s < 4; s++) {
            ps[s] += __shfl_xor_sync(~0u, ps[s], 1);
            ps[s] += __shfl_xor_sync(~0u, ps[s], 2);
            const int row = wm * 32 + (s >> 1) * 16 + (s & 1) * 8 + g;
            if (tg == 0) redS[row * 4 + wn] = ps[s];
        }
        __syncthreads();
#pragma unroll
        for (int s = 0; s < 4; s++) {
            const int row = wm * 32 + (s >> 1) * 16 + (s & 1) * 8 + g;
            const float ts = redS[row * 4] + redS[row * 4 + 1] +
                             redS[row * 4 + 2] + redS[row * 4 + 3];
            l4[s] = alpha[s] * l4[s] + ts;
        }
#pragma unroll
        for (int i = 0; i < 2; i++)
#pragma unroll
            for (int j = 0; j < 4; j++) {
                oacc[i][j][0] *= alpha[i * 2];
                oacc[i][j][1] *= alpha[i * 2];
                oacc[i][j][2] *= alpha[i * 2 + 1];
                oacc[i][j][3] *= alpha[i * 2 + 1];
            }

        // O += P @ V tile: 2 chunks x 4 ks-blocks
        for (int c = 0; c < 2; c++, q++) {
            WAITG1();
            __syncthreads();
            if (q + 2 < 64) issue_body(q + 2);
            COMMIT();
            const uint32_t* Bs = BBuf + (q % 3) * FBBW;
#pragma unroll
            for (int ks4 = 0; ks4 < 4; ks4++) {
                uint32_t af[2][4], bf[4][2];
                const int kk = c * 32 + ks4 * 8 + tg;
#pragma unroll
                for (int i = 0; i < 2; i++) {
                    const int r0 = wm * 32 + i * 16 + g;
                    af[i][0] = Ps[r0 * PSP + kk];
                    af[i][1] = Ps[(r0 + 8) * PSP + kk];
                    af[i][2] = Ps[r0 * PSP + kk + 4];
                    af[i][3] = Ps[(r0 + 8) * PSP + kk + 4];
                }
                const int kl = ks4 * 8 + tg;
#pragma unroll
                for (int j = 0; j < 4; j++) {
                    const int c0 = wn * 32 + j * 8 + g;
                    bf[j][0] = Bs[kl * HPITCH + c0];
                    bf[j][1] = Bs[(kl + 4) * HPITCH + c0];
                }
#pragma unroll
                for (int i = 0; i < 2; i++)
#pragma unroll
                    for (int j = 0; j < 4; j++) MMA_F16(oacc[i][j], af[i], bf[j]);
            }
            __syncthreads();
        }
    }

    float* Oh = O + (size_t)h * 256 * DMOD;
#pragma unroll
    for (int i = 0; i < 2; i++) {
        const int row = by * 64 + wm * 32 + i * 16 + g;
        const float inv0 = 1.f / l4[i * 2];
        const float inv1 = 1.f / l4[i * 2 + 1];
#pragma unroll
        for (int j = 0; j < 4; j++) {
            const int col = wn * 32 + j * 8 + 2 * tg;
            *(float2*)(Oh + (size_t)row * DKH + col) =
                make_float2(oacc[i][j][0] * inv0, oacc[i][j][1] * inv0);
            *(float2*)(Oh + (size_t)(row + 8) * DKH + col) =
                make_float2(oacc[i][j][2] * inv1, oacc[i][j][3] * inv1);
        }
    }
}

// ---- weight pack ----
__global__ void packW_k(const float* __restrict__ W, uint32_t* __restrict__ Wp, int N)
{
    const size_t i = (size_t)blockIdx.x * 256 + threadIdx.x;
    const size_t k2 = i / N, n = i - k2 * N;
    Wp[i] = h2(W[2 * k2 * N + n], W[(2 * k2 + 1) * N + n]);
}

// ---- K/V repack ----
__global__ void packKV_k(const float* __restrict__ qkv,
                         uint32_t* __restrict__ Kp, uint32_t* __restrict__ Vp)
{
    const size_t i = (size_t)blockIdx.x * 256 + threadIdx.x;
    const size_t ND = (size_t)NTOK * DMOD;
    if (blockIdx.z == 0) {
        const int hh = (int)(i >> 17);
        const size_t r = i & 131071;
        const size_t d2 = r >> 11, tk = r & 2047;
        const float* base = qkv + ND + (size_t)hh * 256 * DMOD;
        Kp[i] = h2(base[2 * d2 * 2048 + tk], base[(2 * d2 + 1) * 2048 + tk]);
    } else {
        const int hh = (int)(i >> 17);
        const size_t r = i & 131071;
        const size_t t2 = r >> 7, d = r & 127;
        const float* base = qkv + 2 * ND + (size_t)hh * 256 * DMOD;
        Vp[i] = h2(base[2 * t2 * 128 + d], base[(2 * t2 + 1) * 128 + d]);
    }
}

// ---- split-K reduce (QKV path) ----
__global__ void reduceK_k(const float4* __restrict__ part, float4* __restrict__ outp,
                          const float* __restrict__ bias, int nsplit, size_t MN4,
                          int N4, int sB4)
{
    const size_t i = (size_t)blockIdx.x * blockDim.x + threadIdx.x;
    const size_t b = i / MN4, e = i - b * MN4;
    const float4* p = part + b * (size_t)nsplit * MN4 + e;
    float4 a = p[0];
    for (int s = 1; s < nsplit; s++) {
        const float4 v = p[(size_t)s * MN4];
        a.x += v.x; a.y += v.y; a.z += v.z; a.w += v.w;
    }
    if (bias) {
        const float4 bb = ((const float4*)bias)[b * sB4 + (e % N4)];
        a.x += bb.x; a.y += bb.y; a.z += bb.z; a.w += bb.w;
    }
    outp[i] = a;
}

// ---- fused: y = LayerNorm(resid + part0 + part1 + bias) * g + b ----
__global__ void red_ln_k(const float* __restrict__ part,
                         const float* __restrict__ bias,
                         const float* __restrict__ resid,
                         const float* __restrict__ g, const float* __restrict__ b,
                         float* __restrict__ y)
{
    const int n = blockIdx.x;
    const size_t ND = (size_t)NTOK * DMOD;
    const float4* p0 = (const float4*)(part + (size_t)n * DMOD);
    const float4* p1 = (const float4*)(part + ND + (size_t)n * DMOD);
    const float4* br = (const float4*)bias;
    const float4* rr = (const float4*)(resid + (size_t)n * DMOD);
    const int i = threadIdx.x;
    float4 a = p0[i], c = p1[i], bb = br[i], r = rr[i];
    float v0 = r.x + a.x + c.x + bb.x;
    float v1 = r.y + a.y + c.y + bb.y;
    float v2 = r.z + a.z + c.z + bb.z;
    float v3 = r.w + a.w + c.w + bb.w;

    __shared__ float r1[256], r2[256];
    r1[i] = v0 + v1 + v2 + v3;
    r2[i] = v0 * v0 + v1 * v1 + v2 * v2 + v3 * v3;
    __syncthreads();
    for (int st = 128; st > 0; st >>= 1) {
        if (i < st) { r1[i] += r1[i + st]; r2[i] += r2[i + st]; }
        __syncthreads();
    }
    const float mean = r1[0] * (1.f / DMOD);
    const float var = r2[0] * (1.f / DMOD) - mean * mean;
    const float rstd = rsqrtf(var + 1e-5f);
    const float4 gg = ((const float4*)g)[i];
    const float4 b2v = ((const float4*)b)[i];
    float4 o;
    o.x = (v0 - mean) * rstd * gg.x + b2v.x;
    o.y = (v1 - mean) * rstd * gg.y + b2v.y;
    o.z = (v2 - mean) * rstd * gg.z + b2v.z;
    o.w = (v3 - mean) * rstd * gg.w + b2v.w;
    ((float4*)(y + (size_t)n * DMOD))[i] = o;
}

__global__ void addemb_k(const float* __restrict__ x, const int* __restrict__ ind,
                         const int* __restrict__ outd, const float* __restrict__ ie,
                         const float* __restrict__ oe, float* __restrict__ x2)
{
    const int n = blockIdx.x;
    const float4* xr = (const float4*)(x + (size_t)n * DMOD);
    const float4* ir = (const float4*)(ie + (size_t)ind[n] * DMOD);
    const float4* orr = (const float4*)(oe + (size_t)outd[n] * DMOD);
    const int i = threadIdx.x;
    float4 a = xr[i], b = ir[i], c = orr[i];
    a.x += b.x + c.x; a.y += b.y + c.y; a.z += b.z + c.z; a.w += b.w + c.w;
    ((float4*)(x2 + (size_t)n * DMOD))[i] = a;
}

__global__ void etw_k(const float* __restrict__ re, const float* __restrict__ rw,
                      float* __restrict__ etw)
{
    const int t = threadIdx.x;
    float s = 0.f;
    for (int j = 0; j < DKH; j++) s += re[t * DKH + j] * rw[t * DKH + j];
    etw[t] = s * SCALE;
}

__global__ void bias2d_k(const int* __restrict__ dist, const int4* __restrict__ pet,
                         const float4* __restrict__ paw, const float* __restrict__ plen,
                         const float* __restrict__ etw, float* __restrict__ out)
{
    const size_t i = (size_t)blockIdx.x * blockDim.x + threadIdx.x;
    const int4 e = pet[i];
    const float4 w = paw[i];
    float b = plen[dist[i]];
    b += etw[e.x] * w.x + etw[e.y] * w.y + etw[e.z] * w.z + etw[e.w] * w.w;
    out[i] = b;
}

// ---------------------------------------------------------------------------
extern "C" void kernel_launch(void* const* d_in, const int* in_sizes, int n_in,
                              void* d_out, int out_size)
{
    const float* x      = (const float*)d_in[0];
    const float* lgx    = (const float*)d_in[1];
    const int* in_deg   = (const int*)d_in[2];
    const int* out_deg  = (const int*)d_in[3];
    const int* dist     = (const int*)d_in[4];
    const int* pet      = (const int*)d_in[5];
    const float* paw    = (const float*)d_in[6];
    const float* rel_e  = (const float*)d_in[7];
    const float* rel_w  = (const float*)d_in[8];
    const float* ide    = (const float*)d_in[9];
    const float* ode    = (const float*)d_in[10];
    const float* plen   = (const float*)d_in[11];
    const float* Wq = (const float*)d_in[12];  const float* bq = (const float*)d_in[13];
    const float* Wk = (const float*)d_in[14];  const float* bk = (const float*)d_in[15];
    const float* Wv = (const float*)d_in[16];  const float* bv = (const float*)d_in[17];
    const float* Wo = (const float*)d_in[18];  const float* bo = (const float*)d_in[19];
    const float* ln1g = (const float*)d_in[20]; const float* ln1b = (const float*)d_in[21];
    const float* W1 = (const float*)d_in[22];  const float* b1 = (const float*)d_in[23];
    const float* W2 = (const float*)d_in[24];  const float* b2 = (const float*)d_in[25];
    const float* ln2g = (const float*)d_in[26]; const float* ln2b = (const float*)d_in[27];
    float* out = (float*)d_out;

    float *x2, *bias2d, *bqkv, *qkv, *ao, *h1, *ff, *part, *etw;
    uint32_t *Wqp, *Wop, *W1p, *W2p, *Kp, *Vp;
    cudaGetSymbolAddress((void**)&x2, g_x2);
    cudaGetSymbolAddress((void**)&bias2d, g_bias2d);
    cudaGetSymbolAddress((void**)&bqkv, g_bqkv);
    cudaGetSymbolAddress((void**)&qkv, g_qkv);
    cudaGetSymbolAddress((void**)&ao, g_ao);
    cudaGetSymbolAddress((void**)&h1, g_h1);
    cudaGetSymbolAddress((void**)&ff, g_ff);
    cudaGetSymbolAddress((void**)&part, g_part);
    cudaGetSymbolAddress((void**)&etw, g_etw);
    cudaGetSymbolAddress((void**)&Wqp, g_Wqp);
    cudaGetSymbolAddress((void**)&Wop, g_Wop);
    cudaGetSymbolAddress((void**)&W1p, g_W1p);
    cudaGetSymbolAddress((void**)&W2p, g_W2p);
    cudaGetSymbolAddress((void**)&Kp, g_Kp);
    cudaGetSymbolAddress((void**)&Vp, g_Vp);

    cudaFuncSetAttribute(hgemm, cudaFuncAttributeMaxDynamicSharedMemorySize,
                         HSMEM_BYTES);
    cudaFuncSetAttribute(flash_h, cudaFuncAttributeMaxDynamicSharedMemorySize,
                         FLASH_SMEM);

    static cudaStream_t s2 = nullptr;
    static cudaEvent_t evFork = nullptr, evJoin = nullptr;
    if (!s2) {
        cudaStreamCreateWithFlags(&s2, cudaStreamNonBlocking);
        cudaEventCreateWithFlags(&evFork, cudaEventDisableTiming);
        cudaEventCreateWithFlags(&evJoin, cudaEventDisableTiming);
    }

    const size_t ND = (size_t)NTOK * DMOD;
    const int WQW = 512 * DMOD;

    // fork: side stream does lgx copy + etw + bias2d + late weight packs
    cudaEventRecord(evFork, 0);
    cudaStreamWaitEvent(s2, evFork, 0);
    cudaMemcpyAsync(out + ND, lgx, (size_t)NTOK * 8 * DMOD * sizeof(float),
                    cudaMemcpyDeviceToDevice, s2);
    etw_k<<<1, 64, 0, s2>>>(rel_e, rel_w, etw);
    bias2d_k<<<(NTOK * NTOK) / 256, 256, 0, s2>>>(
        dist, (const int4*)pet, (const float4*)paw, plen, etw, bias2d);
    packW_k<<<WQW / 256, 256, 0, s2>>>(Wo, Wop, DMOD);
    packW_k<<<512 * FFD / 256, 256, 0, s2>>>(W1, W1p, FFD);
    packW_k<<<2048 * DMOD / 256, 256, 0, s2>>>(W2, W2p, DMOD);
    cudaEventRecord(evJoin, s2);

    // main: QKV weight packs, biases, addemb
    packW_k<<<WQW / 256, 256>>>(Wq, Wqp, DMOD);
    packW_k<<<WQW / 256, 256>>>(Wk, Wqp + WQW, DMOD);
    packW_k<<<WQW / 256, 256>>>(Wv, Wqp + 2 * WQW, DMOD);
    cudaMemcpyAsync(bqkv,            bq, DMOD * 4, cudaMemcpyDeviceToDevice);
    cudaMemcpyAsync(bqkv + DMOD,     bk, DMOD * 4, cudaMemcpyDeviceToDevice);
    cudaMemcpyAsync(bqkv + 2 * DMOD, bv, DMOD * 4, cudaMemcpyDeviceToDevice);
    addemb_k<<<NTOK, 256>>>(x, in_deg, out_deg, ide, ode, x2);

    // QKV: split-K=2, 3 batches -> partials, reduce(+bqkv)
    hgemm<<<dim3(8, 16, 6), 256, HSMEM_BYTES>>>(
        x2, Wqp, nullptr, part, NTOK, DMOD, DMOD,
        0, (size_t)WQW, ND, 0, 0, 2);
    reduceK_k<<<(int)(3 * ND / 4 / 256), 256>>>(
        (const float4*)part, (float4*)qkv, bqkv, 2, ND / 4, DMOD / 4, DMOD / 4);

    // repack K,V to half2
    packKV_k<<<dim3(HEADS * 64 * NTOK / 256, 1, 2), 256>>>(qkv, Kp, Vp);

    // join: flash needs bias2d (and late packs must be done before Wo gemm)
    cudaStreamWaitEvent(0, evJoin, 0);
    flash_h<<<dim3(1, 32, HEADS), 256, FLASH_SMEM>>>(qkv, Kp, Vp, bias2d, ao);

    // Wo: split-K=2 -> partials; fused reduce+bo+residual(x2)+LN1 -> h1
    hgemm<<<dim3(8, 16, 2), 256, HSMEM_BYTES>>>(
        ao, Wop, nullptr, part, NTOK, DMOD, DMOD, 0, 0, ND, 0, 0, 2);
    red_ln_k<<<NTOK, 256>>>(part, bo, x2, ln1g, ln1b, h1);

    // FFN1 (+b1, relu)
    hgemm<<<dim3(32, 16, 1), 256, HSMEM_BYTES>>>(
        h1, W1p, b1, ff, NTOK, FFD, DMOD, 0, 0, 0, FFD, 1, 1);
    // FFN2: split-K=2 -> partials; fused reduce+b2+residual(h1)+LN2 -> out
    hgemm<<<dim3(8, 16, 2), 256, HSMEM_BYTES>>>(
        ff, W2p, nullptr, part, NTOK, DMOD, FFD, 0, 0, ND, 0, 0, 2);
    red_ln_k<<<NTOK, 256>>>(part, b2, h1, ln2g, ln2b, out);
}

// round 14
// speedup vs baseline: 1.5481x; 1.0421x over previous
#include <cuda_runtime.h>
#include <cuda_fp16.h>
#include <cstdint>
#include <cstddef>

// ---------------------------------------------------------------------------
// Rel_Transformer_Layer: N=2048, D=1024, H=8, DK=128, L=4, FF=4096
// Round 14: R13 + QKV as single N=3072 fused GEMM (no split-K partials/reduce,
// bias in epilogue, column-split output into q/k/v regions).
// ---------------------------------------------------------------------------

#define NTOK 2048
#define DMOD 1024
#define HEADS 8
#define DKH 128
#define FFD 4096
#define SCALE 0.08838834764831845f

// -------------------- scratch ------------------
__device__ float g_x2[NTOK * DMOD];
__device__ float g_bias2d[(size_t)NTOK * NTOK];
__device__ float g_bqkv[3 * DMOD];
__device__ float g_qkv[3 * NTOK * DMOD];
__device__ float g_ao[NTOK * DMOD];
__device__ float g_h1[NTOK * DMOD];
__device__ float g_ff[(size_t)NTOK * FFD];
__device__ float g_part[(size_t)2 * NTOK * DMOD];
__device__ float g_etw[64];
__device__ uint32_t g_Wqp[512 * 3 * DMOD];     // [512][3072] packed half2
__device__ uint32_t g_Wop[512 * DMOD];
__device__ uint32_t g_W1p[512 * FFD];
__device__ uint32_t g_W2p[2048 * DMOD];
__device__ uint32_t g_Kp[HEADS * 64 * NTOK];   // [h][dk/2][tok]
__device__ uint32_t g_Vp[HEADS * 1024 * DKH];  // [h][tok/2][dk]

// -------------------- helpers ------------------
__device__ __forceinline__ uint32_t h2(float a, float b) {
    __half2 h = __floats2half2_rn(a, b);
    return *(uint32_t*)&h;
}
__device__ __forceinline__ void cpasync16(uint32_t s, const void* g) {
    asm volatile("cp.async.cg.shared.global [%0], [%1], 16;" :: "r"(s), "l"(g));
}
#define COMMIT() asm volatile("cp.async.commit_group;" ::: "memory")
#define WAITG1() asm volatile("cp.async.wait_group 1;" ::: "memory")

#define MMA_F16(acc, af, bf)                                               \
    asm volatile(                                                          \
        "mma.sync.aligned.m16n8k16.row.col.f32.f16.f16.f32 "               \
        "{%0,%1,%2,%3}, {%4,%5,%6,%7}, {%8,%9}, {%0,%1,%2,%3};"            \
        : "+f"(acc[0]), "+f"(acc[1]), "+f"(acc[2]), "+f"(acc[3])           \
        : "r"(af[0]), "r"(af[1]), "r"(af[2]), "r"(af[3]),                  \
          "r"(bf[0]), "r"(bf[1]))

#define AFW1H 2048
__device__ __forceinline__ void storeA_h(
    uint32_t* AFb, const float4 A0[2], const float4 A1[2],
    int wmS, int iS, int g, int tg)
{
#pragma unroll
    for (int ks = 0; ks < 2; ks++) {
        const float* f0 = (const float*)&A0[ks];
        const float* f1 = (const float*)&A1[ks];
#pragma unroll
        for (int pp = 0; pp < 2; pp++) {
            const int kp = 2 * tg + pp;
            const int tgp = kp & 3;
            const int hk = kp >> 2;
            const uint32_t w0 = h2(f0[2 * pp], f0[2 * pp + 1]);
            const uint32_t w1 = h2(f1[2 * pp], f1[2 * pp + 1]);
            const int idx = (((wmS * 2 + ks) * 4 + iS) * 32 +
                             ((g * 4 + tgp) ^ (g & 3))) * 4 + 2 * hk;
            *(uint2*)&AFb[idx] = make_uint2(w0, w1);
        }
    }
}

// 64-row variant (R13 verified)
__device__ __forceinline__ void storeA_h64(
    uint32_t* AFb, const float4 A0, const float4 A1,
    int wmS, int iS, int par, int g, int tg)
{
    const float4 A[2] = {A0, A1};
#pragma unroll
    for (int ks = 0; ks < 2; ks++) {
        const float* f = (const float*)&A[ks];
#pragma unroll
        for (int pp = 0; pp < 2; pp++) {
            const int kp = 2 * tg + pp;
            const int tgp = kp & 3;
            const int hk = kp >> 2;
            const uint32_t w = h2(f[2 * pp], f[2 * pp + 1]);
            const int idx = (((wmS * 2 + ks) * 2 + iS) * 32 +
                             ((g * 4 + tgp) ^ (g & 3))) * 4 + 2 * hk + par;
            AFb[idx] = w;
        }
    }
}

// ==================== fp16 GEMM ====================
// splitCols != 0: output column c goes to C + (c/splitCols)*sC, local col
// c % splitCols with row pitch splitCols (used for fused QKV, splitCols=1024).
#define HPITCH 136
#define HBBW (16 * HPITCH)
#define HSMEM_BYTES ((2 * AFW1H + 3 * HBBW) * 4)

__global__ __launch_bounds__(256, 2) void hgemm(
    const float* __restrict__ A, const uint32_t* __restrict__ Bp,
    const float* __restrict__ biasvec, float* __restrict__ C,
    int M, int N, int K, size_t sA, size_t sBp, size_t sC, size_t sBias,
    int doRelu, int nsplit, int splitCols)
{
    extern __shared__ uint32_t sm[];
    uint32_t* AF = sm;
    uint32_t* BBuf = sm + 2 * AFW1H;

    const int tid = threadIdx.x, wid = tid >> 5, lane = tid & 31;
    const int g = lane >> 2, tg = lane & 3, wm = wid >> 2, wn = wid & 3;
    const int batch = blockIdx.z / nsplit, split = blockIdx.z - batch * nsplit;
    const int Keff = K / nsplit, nIter = Keff / 32;

    const float* Ab = A + (size_t)batch * sA + (size_t)split * Keff
                        + (size_t)blockIdx.y * 128 * K;
    const uint32_t* Bb = Bp + (size_t)batch * sBp
                        + (size_t)(split * Keff / 2) * N + (size_t)blockIdx.x * 128;
    float* Cb = C + (size_t)blockIdx.z * sC;
    const float* bvv = biasvec ? biasvec + (size_t)batch * sBias : nullptr;

    const int wmS = wid >> 2, iS = wid & 3;
    const float* Ag0 = Ab + (size_t)(wid * 16 + g) * K + tg * 4;
    const float* Ag1 = Ag0 + (size_t)8 * K;

    const int bRow = tid >> 5;
    const int bCol = (tid & 31) << 2;
    const uint32_t* Bg = Bb + (size_t)bRow * N + bCol;
    const uint32_t bSh = (uint32_t)__cvta_generic_to_shared(BBuf);

    float4 A0[2], A1[2];
    A0[0] = *(const float4*)(Ag0);       A0[1] = *(const float4*)(Ag0 + 16);
    A1[0] = *(const float4*)(Ag1);       A1[1] = *(const float4*)(Ag1 + 16);
    storeA_h(AF, A0, A1, wmS, iS, g, tg);
#pragma unroll
    for (int rh = 0; rh < 16; rh += 8)
        cpasync16(bSh + (((bRow + rh) * HPITCH + bCol) << 2), Bg + (size_t)rh * N);
    COMMIT();
    A0[0] = *(const float4*)(Ag0 + 32);  A0[1] = *(const float4*)(Ag0 + 48);
    A1[0] = *(const float4*)(Ag1 + 32);  A1[1] = *(const float4*)(Ag1 + 48);
    {
        const uint32_t* Bn = Bg + (size_t)16 * N;
        const uint32_t db = bSh + (HBBW << 2);
#pragma unroll
        for (int rh = 0; rh < 16; rh += 8)
            cpasync16(db + (((bRow + rh) * HPITCH + bCol) << 2), Bn + (size_t)rh * N);
    }
    COMMIT();

    float acc[4][4][4];
#pragma unroll
    for (int i = 0; i < 4; i++)
#pragma unroll
        for (int j = 0; j < 4; j++)
#pragma unroll
            for (int r = 0; r < 4; r++) acc[i][j][r] = 0.f;

    for (int it = 0; it < nIter; it++) {
        WAITG1();
        __syncthreads();
        if (it + 2 < nIter) {
            const uint32_t* Bn = Bg + (size_t)(it + 2) * 16 * N;
            const uint32_t db = bSh + (((it + 2) % 3) * HBBW << 2);
#pragma unroll
            for (int rh = 0; rh < 16; rh += 8)
                cpasync16(db + (((bRow + rh) * HPITCH + bCol) << 2), Bn + (size_t)rh * N);
        }
        COMMIT();
        if (it + 1 < nIter)
            storeA_h(AF + ((it + 1) & 1) * AFW1H, A0, A1, wmS, iS, g, tg);
        if (it + 2 < nIter) {
            const float* An0 = Ag0 + (size_t)(it + 2) * 32;
            const float* An1 = Ag1 + (size_t)(it + 2) * 32;
            A0[0] = *(const float4*)(An0);  A0[1] = *(const float4*)(An0 + 16);
            A1[0] = *(const float4*)(An1);  A1[1] = *(const float4*)(An1 + 16);
        }
        const uint32_t* AFr = AF + (it & 1) * AFW1H;
        const uint32_t* Bs = BBuf + (it % 3) * HBBW;
#pragma unroll
        for (int ks = 0; ks < 2; ks++) {
            uint32_t af[4][4], bf[4][2];
#pragma unroll
            for (int i = 0; i < 4; i++) {
                const uint4 qd = *(const uint4*)
                    &AFr[(((wm * 2 + ks) * 4 + i) * 32 + (lane ^ (g & 3))) * 4];
                af[i][0] = qd.x; af[i][1] = qd.y; af[i][2] = qd.z; af[i][3] = qd.w;
            }
            const int kl = ks * 8 + tg;
#pragma unroll
            for (int j = 0; j < 4; j++) {
                const int c0 = wn * 32 + j * 8 + g;
                bf[j][0] = Bs[kl * HPITCH + c0];
                bf[j][1] = Bs[(kl + 4) * HPITCH + c0];
            }
#pragma unroll
            for (int i = 0; i < 4; i++)
#pragma unroll
                for (int j = 0; j < 4; j++) MMA_F16(acc[i][j], af[i], bf[j]);
        }
        __syncthreads();
    }

#pragma unroll
    for (int i = 0; i < 4; i++) {
        const int row = blockIdx.y * 128 + wm * 64 + i * 16 + g;
#pragma unroll
        for (int j = 0; j < 4; j++) {
            const int col = blockIdx.x * 128 + wn * 32 + j * 8 + 2 * tg;
            float v0 = acc[i][j][0], v1 = acc[i][j][1];
            float v2 = acc[i][j][2], v3 = acc[i][j][3];
            if (bvv) {
                v0 += bvv[col]; v1 += bvv[col + 1];
                v2 += bvv[col]; v3 += bvv[col + 1];
            }
            if (doRelu) {
                v0 = fmaxf(v0, 0.f); v1 = fmaxf(v1, 0.f);
                v2 = fmaxf(v2, 0.f); v3 = fmaxf(v3, 0.f);
            }
            float* Cw;
            int pitch;
            if (splitCols) {
                const int cb = col / splitCols;
                Cw = C + (size_t)cb * sC + (size_t)row * splitCols
                       + (col - cb * splitCols);
                pitch = splitCols;
            } else {
                Cw = Cb + (size_t)row * N + col;
                pitch = N;
            }
            *(float2*)(Cw) = make_float2(v0, v1);
            *(float2*)(Cw + (size_t)8 * pitch) = make_float2(v2, v3);
        }
    }
}

// ==================== fp16 flash, 64-row blocks, occ 2 (R13) ================
#define FBBW (32 * HPITCH)
#define PSP 68
#define F6_BB  4096
#define F6_PS  (F6_BB + 3 * FBBW)
#define F6_RED (F6_PS + 64 * PSP)
#define FLASH_SMEM ((F6_RED + 512) * 4)

__global__ __launch_bounds__(256, 2) void flash_h(
    const float* __restrict__ Q, const uint32_t* __restrict__ Kp,
    const uint32_t* __restrict__ Vp, const float* __restrict__ bias2d,
    float* __restrict__ O)
{
    extern __shared__ uint32_t sm[];
    uint32_t* AFQ = sm;
    uint32_t* BBuf = sm + F6_BB;
    uint32_t* Ps = sm + F6_PS;
    float* redM = (float*)(sm + F6_RED);
    float* redS = redM + 256;

    const int tid = threadIdx.x, wid = tid >> 5, lane = tid & 31;
    const int g = lane >> 2, tg = lane & 3, wm = wid >> 2, wn = wid & 3;
    const int h = blockIdx.z, by = blockIdx.y;

    const float* Qh = Q + (size_t)h * 256 * DMOD;
    const uint32_t* Kh = Kp + (size_t)h * 64 * NTOK;
    const uint32_t* Vh = Vp + (size_t)h * 1024 * DKH;

    const int bRow = tid >> 5, bCol = (tid & 31) << 2;
    const uint32_t bSh = (uint32_t)__cvta_generic_to_shared(BBuf);
    auto issue_body = [&](int qq) {
        const int t = qq >> 2, ph = qq & 3;
        const uint32_t* src;
        int stride;
        if (ph < 2) { src = Kh + (size_t)(ph * 32 + bRow) * NTOK + t * 128 + bCol; stride = NTOK; }
        else        { src = Vh + (size_t)(t * 64 + (ph - 2) * 32 + bRow) * DKH + bCol; stride = DKH; }
        const uint32_t db = bSh + ((qq % 3) * FBBW << 2);
#pragma unroll
        for (int rh = 0; rh < 32; rh += 8)
            cpasync16(db + (((bRow + rh) * HPITCH + bCol) << 2), src + (size_t)rh * stride);
    };
    issue_body(0); COMMIT();
    issue_body(1); COMMIT();

    {
        const int blk = wid >> 1, par = wid & 1;
        const int wmS = blk >> 1, iS = blk & 1;
        const float* Qg = Qh + (size_t)(by * 64 + wid * 8 + g) * DKH + tg * 4;
#pragma unroll
        for (int c = 0; c < 4; c++) {
            const float4 A0 = *(const float4*)(Qg + c * 32);
            const float4 A1 = *(const float4*)(Qg + c * 32 + 16);
            storeA_h64(AFQ + c * 1024, A0, A1, wmS, iS, par, g, tg);
        }
    }

    float m4[4], l4[4], oacc[2][4][4];
#pragma unroll
    for (int s = 0; s < 4; s++) { m4[s] = -1e30f; l4[s] = 0.f; }
#pragma unroll
    for (int i = 0; i < 2; i++)
#pragma unroll
        for (int j = 0; j < 4; j++)
#pragma unroll
            for (int r = 0; r < 4; r++) oacc[i][j][r] = 0.f;

    int q = 0;
    for (int t = 0; t < 16; t++) {
        float sacc[2][4][4];
#pragma unroll
        for (int i = 0; i < 2; i++)
#pragma unroll
            for (int j = 0; j < 4; j++)
#pragma unroll
                for (int r = 0; r < 4; r++) sacc[i][j][r] = 0.f;

        for (int c = 0; c < 2; c++, q++) {
            WAITG1();
            __syncthreads();
            if (q + 2 < 64) issue_body(q + 2);
            COMMIT();
            const uint32_t* Bs = BBuf + (q % 3) * FBBW;
#pragma unroll
            for (int ks4 = 0; ks4 < 4; ks4++) {
                const uint32_t* AFr = AFQ + (c * 2 + (ks4 >> 1)) * 1024;
                const int ks = ks4 & 1;
                uint32_t af[2][4], bf[4][2];
#pragma unroll
                for (int i = 0; i < 2; i++) {
                    const uint4 qd = *(const uint4*)
                        &AFr[(((wm * 2 + ks) * 2 + i) * 32 + (lane ^ (g & 3))) * 4];
                    af[i][0] = qd.x; af[i][1] = qd.y; af[i][2] = qd.z; af[i][3] = qd.w;
                }
                const int kl = ks4 * 8 + tg;
#pragma unroll
                for (int j = 0; j < 4; j++) {
                    const int c0 = wn * 32 + j * 8 + g;
                    bf[j][0] = Bs[kl * HPITCH + c0];
                    bf[j][1] = Bs[(kl + 4) * HPITCH + c0];
                }
#pragma unroll
                for (int i = 0; i < 2; i++)
#pragma unroll
                    for (int j = 0; j < 4; j++) MMA_F16(sacc[i][j], af[i], bf[j]);
            }
            __syncthreads();
        }

#pragma unroll
        for (int i = 0; i < 2; i++) {
            const int rg = by * 64 + wm * 32 + i * 16 + g;
#pragma unroll
            for (int j = 0; j < 4; j++) {
                const int cg = t * 128 + wn * 32 + j * 8 + 2 * tg;
                const float2 b0 = *(const float2*)(bias2d + (size_t)rg * NTOK + cg);
                const float2 b1 = *(const float2*)(bias2d + (size_t)(rg + 8) * NTOK + cg);
                sacc[i][j][0] = sacc[i][j][0] * SCALE + b0.x;
                sacc[i][j][1] = sacc[i][j][1] * SCALE + b0.y;
                sacc[i][j][2] = sacc[i][j][2] * SCALE + b1.x;
                sacc[i][j][3] = sacc[i][j][3] * SCALE + b1.y;
            }
        }

        float pm[4];
#pragma unroll
        for (int i = 0; i < 2; i++)
#pragma unroll
            for (int h2i = 0; h2i < 2; h2i++) {
                float v = -1e30f;
#pragma unroll
                for (int j = 0; j < 4; j++)
                    v = fmaxf(v, fmaxf(sacc[i][j][2 * h2i], sacc[i][j][2 * h2i + 1]));
                pm[i * 2 + h2i] = v;
            }
#pragma unroll
        for (int s = 0; s < 4; s++) {
            pm[s] = fmaxf(pm[s], __shfl_xor_sync(~0u, pm[s], 1));
            pm[s] = fmaxf(pm[s], __shfl_xor_sync(~0u, pm[s], 2));
        }
#pragma unroll
        for (int s = 0; s < 4; s++) {
            const int row = wm * 32 + (s >> 1) * 16 + (s & 1) * 8 + g;
            if (tg == 0) redM[row * 4 + wn] = pm[s];
        }
        __syncthreads();

        float alpha[4], nm[4];
#pragma unroll
        for (int s = 0; s < 4; s++) {
            const int row = wm * 32 + (s >> 1) * 16 + (s & 1) * 8 + g;
            float tm = fmaxf(fmaxf(redM[row * 4], redM[row * 4 + 1]),
                             fmaxf(redM[row * 4 + 2], redM[row * 4 + 3]));
            nm[s] = fmaxf(m4[s], tm);
            alpha[s] = __expf(m4[s] - nm[s]);
            m4[s] = nm[s];
        }

        float ps[4];
#pragma unroll
        for (int s = 0; s < 4; s++) ps[s] = 0.f;
#pragma unroll
        for (int i = 0; i < 2; i++)
#pragma unroll
            for (int h2i = 0; h2i < 2; h2i++) {
                const int row = wm * 32 + i * 16 + h2i * 8 + g;
#pragma unroll
                for (int j = 0; j < 4; j++) {
                    const int cw = wn * 16 + j * 4 + tg;
                    float p0 = __expf(sacc[i][j][2 * h2i] - nm[i * 2 + h2i]);
                    float p1 = __expf(sacc[i][j][2 * h2i + 1] - nm[i * 2 + h2i]);
                    ps[i * 2 + h2i] += p0 + p1;
                    Ps[row * PSP + cw] = h2(p0, p1);
                }
            }
#pragma unroll
        for (int s = 0; s < 4; s++) {
            ps[s] += __shfl_xor_sync(~0u, ps[s], 1);
            ps[s] += __shfl_xor_sync(~0u, ps[s], 2);
            const int row = wm * 32 + (s >> 1) * 16 + (s & 1) * 8 + g;
            if (tg == 0) redS[row * 4 + wn] = ps[s];
        }
        __syncthreads();
#pragma unroll
        for (int s = 0; s < 4; s++) {
            const int row = wm * 32 + (s >> 1) * 16 + (s & 1) * 8 + g;
            const float ts = redS[row * 4] + redS[row * 4 + 1] +
                             redS[row * 4 + 2] + redS[row * 4 + 3];
            l4[s] = alpha[s] * l4[s] + ts;
        }
#pragma unroll
        for (int i = 0; i < 2; i++)
#pragma unroll
            for (int j = 0; j < 4; j++) {
                oacc[i][j][0] *= alpha[i * 2];
                oacc[i][j][1] *= alpha[i * 2];
                oacc[i][j][2] *= alpha[i * 2 + 1];
                oacc[i][j][3] *= alpha[i * 2 + 1];
            }

        for (int c = 0; c < 2; c++, q++) {
            WAITG1();
            __syncthreads();
            if (q + 2 < 64) issue_body(q + 2);
            COMMIT();
            const uint32_t* Bs = BBuf + (q % 3) * FBBW;
#pragma unroll
            for (int ks4 = 0; ks4 < 4; ks4++) {
                uint32_t af[2][4], bf[4][2];
                const int kk = c * 32 + ks4 * 8 + tg;
#pragma unroll
                for (int i = 0; i < 2; i++) {
                    const int r0 = wm * 32 + i * 16 + g;
                    af[i][0] = Ps[r0 * PSP + kk];
                    af[i][1] = Ps[(r0 + 8) * PSP + kk];
                    af[i][2] = Ps[r0 * PSP + kk + 4];
                    af[i][3] = Ps[(r0 + 8) * PSP + kk + 4];
                }
                const int kl = ks4 * 8 + tg;
#pragma unroll
                for (int j = 0; j < 4; j++) {
                    const int c0 = wn * 32 + j * 8 + g;
                    bf[j][0] = Bs[kl * HPITCH + c0];
                    bf[j][1] = Bs[(kl + 4) * HPITCH + c0];
                }
#pragma unroll
                for (int i = 0; i < 2; i++)
#pragma unroll
                    for (int j = 0; j < 4; j++) MMA_F16(oacc[i][j], af[i], bf[j]);
            }
            __syncthreads();
        }
    }

    float* Oh = O + (size_t)h * 256 * DMOD;
#pragma unroll
    for (int i = 0; i < 2; i++) {
        const int row = by * 64 + wm * 32 + i * 16 + g;
        const float inv0 = 1.f / l4[i * 2];
        const float inv1 = 1.f / l4[i * 2 + 1];
#pragma unroll
        for (int j = 0; j < 4; j++) {
            const int col = wn * 32 + j * 8 + 2 * tg;
            *(float2*)(Oh + (size_t)row * DKH + col) =
                make_float2(oacc[i][j][0] * inv0, oacc[i][j][1] * inv0);
            *(float2*)(Oh + (size_t)(row + 8) * DKH + col) =
                make_float2(oacc[i][j][2] * inv1, oacc[i][j][3] * inv1);
        }
    }
}

// ---- weight pack: Wp[k2*NS + off + n] = half2(W[2k2][n], W[2k2+1][n]) ----
__global__ void packW_k(const float* __restrict__ W, uint32_t* __restrict__ Wp,
                        int N, int NS, int off)
{
    const size_t i = (size_t)blockIdx.x * 256 + threadIdx.x;
    const size_t k2 = i / N, n = i - k2 * N;
    Wp[k2 * NS + off + n] = h2(W[2 * k2 * N + n], W[(2 * k2 + 1) * N + n]);
}

// ---- K/V repack ----
__global__ void packKV_k(const float* __restrict__ qkv,
                         uint32_t* __restrict__ Kp, uint32_t* __restrict__ Vp)
{
    const size_t i = (size_t)blockIdx.x * 256 + threadIdx.x;
    const size_t ND = (size_t)NTOK * DMOD;
    if (blockIdx.z == 0) {
        const int hh = (int)(i >> 17);
        const size_t r = i & 131071;
        const size_t d2 = r >> 11, tk = r & 2047;
        const float* base = qkv + ND + (size_t)hh * 256 * DMOD;
        Kp[i] = h2(base[2 * d2 * 2048 + tk], base[(2 * d2 + 1) * 2048 + tk]);
    } else {
        const int hh = (int)(i >> 17);
        const size_t r = i & 131071;
        const size_t t2 = r >> 7, d = r & 127;
        const float* base = qkv + 2 * ND + (size_t)hh * 256 * DMOD;
        Vp[i] = h2(base[2 * t2 * 128 + d], base[(2 * t2 + 1) * 128 + d]);
    }
}

// ---- fused: y = LayerNorm(resid + part0 + part1 + bias) * g + b ----
__global__ void red_ln_k(const float* __restrict__ part,
                         const float* __restrict__ bias,
                         const float* __restrict__ resid,
                         const float* __restrict__ g, const float* __restrict__ b,
                         float* __restrict__ y)
{
    const int n = blockIdx.x;
    const size_t ND = (size_t)NTOK * DMOD;
    const float4* p0 = (const float4*)(part + (size_t)n * DMOD);
    const float4* p1 = (const float4*)(part + ND + (size_t)n * DMOD);
    const float4* br = (const float4*)bias;
    const float4* rr = (const float4*)(resid + (size_t)n * DMOD);
    const int i = threadIdx.x;
    float4 a = p0[i], c = p1[i], bb = br[i], r = rr[i];
    float v0 = r.x + a.x + c.x + bb.x;
    float v1 = r.y + a.y + c.y + bb.y;
    float v2 = r.z + a.z + c.z + bb.z;
    float v3 = r.w + a.w + c.w + bb.w;

    __shared__ float r1[256], r2[256];
    r1[i] = v0 + v1 + v2 + v3;
    r2[i] = v0 * v0 + v1 * v1 + v2 * v2 + v3 * v3;
    __syncthreads();
    for (int st = 128; st > 0; st >>= 1) {
        if (i < st) { r1[i] += r1[i + st]; r2[i] += r2[i + st]; }
        __syncthreads();
    }
    const float mean = r1[0] * (1.f / DMOD);
    const float var = r2[0] * (1.f / DMOD) - mean * mean;
    const float rstd = rsqrtf(var + 1e-5f);
    const float4 gg = ((const float4*)g)[i];
    const float4 b2v = ((const float4*)b)[i];
    float4 o;
    o.x = (v0 - mean) * rstd * gg.x + b2v.x;
    o.y = (v1 - mean) * rstd * gg.y + b2v.y;
    o.z = (v2 - mean) * rstd * gg.z + b2v.z;
    o.w = (v3 - mean) * rstd * gg.w + b2v.w;
    ((float4*)(y + (size_t)n * DMOD))[i] = o;
}

__global__ void addemb_k(const float* __restrict__ x, const int* __restrict__ ind,
                         const int* __restrict__ outd, const float* __restrict__ ie,
                         const float* __restrict__ oe, float* __restrict__ x2)
{
    const int n = blockIdx.x;
    const float4* xr = (const float4*)(x + (size_t)n * DMOD);
    const float4* ir = (const float4*)(ie + (size_t)ind[n] * DMOD);
    const float4* orr = (const float4*)(oe + (size_t)outd[n] * DMOD);
    const int i = threadIdx.x;
    float4 a = xr[i], b = ir[i], c = orr[i];
    a.x += b.x + c.x; a.y += b.y + c.y; a.z += b.z + c.z; a.w += b.w + c.w;
    ((float4*)(x2 + (size_t)n * DMOD))[i] = a;
}

__global__ void etw_k(const float* __restrict__ re, const float* __restrict__ rw,
                      float* __restrict__ etw)
{
    const int t = threadIdx.x;
    float s = 0.f;
    for (int j = 0; j < DKH; j++) s += re[t * DKH + j] * rw[t * DKH + j];
    etw[t] = s * SCALE;
}

__global__ void bias2d_k(const int* __restrict__ dist, const int4* __restrict__ pet,
                         const float4* __restrict__ paw, const float* __restrict__ plen,
                         const float* __restrict__ etw, float* __restrict__ out)
{
    const size_t i = (size_t)blockIdx.x * blockDim.x + threadIdx.x;
    const int4 e = pet[i];
    const float4 w = paw[i];
    float b = plen[dist[i]];
    b += etw[e.x] * w.x + etw[e.y] * w.y + etw[e.z] * w.z + etw[e.w] * w.w;
    out[i] = b;
}

// ---------------------------------------------------------------------------
extern "C" void kernel_launch(void* const* d_in, const int* in_sizes, int n_in,
                              void* d_out, int out_size)
{
    const float* x      = (const float*)d_in[0];
    const float* lgx    = (const float*)d_in[1];
    const int* in_deg   = (const int*)d_in[2];
    const int* out_deg  = (const int*)d_in[3];
    const int* dist     = (const int*)d_in[4];
    const int* pet      = (const int*)d_in[5];
    const float* paw    = (const float*)d_in[6];
    const float* rel_e  = (const float*)d_in[7];
    const float* rel_w  = (const float*)d_in[8];
    const float* ide    = (const float*)d_in[9];
    const float* ode    = (const float*)d_in[10];
    const float* plen   = (const float*)d_in[11];
    const float* Wq = (const float*)d_in[12];  const float* bq = (const float*)d_in[13];
    const float* Wk = (const float*)d_in[14];  const float* bk = (const float*)d_in[15];
    const float* Wv = (const float*)d_in[16];  const float* bv = (const float*)d_in[17];
    const float* Wo = (const float*)d_in[18];  const float* bo = (const float*)d_in[19];
    const float* ln1g = (const float*)d_in[20]; const float* ln1b = (const float*)d_in[21];
    const float* W1 = (const float*)d_in[22];  const float* b1 = (const float*)d_in[23];
    const float* W2 = (const float*)d_in[24];  const float* b2 = (const float*)d_in[25];
    const float* ln2g = (const float*)d_in[26]; const float* ln2b = (const float*)d_in[27];
    float* out = (float*)d_out;

    float *x2, *bias2d, *bqkv, *qkv, *ao, *h1, *ff, *part, *etw;
    uint32_t *Wqp, *Wop, *W1p, *W2p, *Kp, *Vp;
    cudaGetSymbolAddress((void**)&x2, g_x2);
    cudaGetSymbolAddress((void**)&bias2d, g_bias2d);
    cudaGetSymbolAddress((void**)&bqkv, g_bqkv);
    cudaGetSymbolAddress((void**)&qkv, g_qkv);
    cudaGetSymbolAddress((void**)&ao, g_ao);
    cudaGetSymbolAddress((void**)&h1, g_h1);
    cudaGetSymbolAddress((void**)&ff, g_ff);
    cudaGetSymbolAddress((void**)&part, g_part);
    cudaGetSymbolAddress((void**)&etw, g_etw);
    cudaGetSymbolAddress((void**)&Wqp, g_Wqp);
    cudaGetSymbolAddress((void**)&Wop, g_Wop);
    cudaGetSymbolAddress((void**)&W1p, g_W1p);
    cudaGetSymbolAddress((void**)&W2p, g_W2p);
    cudaGetSymbolAddress((void**)&Kp, g_Kp);
    cudaGetSymbolAddress((void**)&Vp, g_Vp);

    cudaFuncSetAttribute(hgemm, cudaFuncAttributeMaxDynamicSharedMemorySize,
                         HSMEM_BYTES);
    cudaFuncSetAttribute(flash_h, cudaFuncAttributeMaxDynamicSharedMemorySize,
                         FLASH_SMEM);

    static cudaStream_t s2 = nullptr;
    static cudaEvent_t evFork = nullptr, evJoin = nullptr;
    if (!s2) {
        cudaStreamCreateWithFlags(&s2, cudaStreamNonBlocking);
        cudaEventCreateWithFlags(&evFork, cudaEventDisableTiming);
        cudaEventCreateWithFlags(&evJoin, cudaEventDisableTiming);
    }

    const size_t ND = (size_t)NTOK * DMOD;
    const int WQW = 512 * DMOD;
    const int N3 = 3 * DMOD;   // 3072

    // fork: side stream does lgx copy + etw + bias2d + late weight packs
    cudaEventRecord(evFork, 0);
    cudaStreamWaitEvent(s2, evFork, 0);
    cudaMemcpyAsync(out + ND, lgx, (size_t)NTOK * 8 * DMOD * sizeof(float),
                    cudaMemcpyDeviceToDevice, s2);
    etw_k<<<1, 64, 0, s2>>>(rel_e, rel_w, etw);
    bias2d_k<<<(NTOK * NTOK) / 256, 256, 0, s2>>>(
        dist, (const int4*)pet, (const float4*)paw, plen, etw, bias2d);
    packW_k<<<WQW / 256, 256, 0, s2>>>(Wo, Wop, DMOD, DMOD, 0);
    packW_k<<<512 * FFD / 256, 256, 0, s2>>>(W1, W1p, FFD, FFD, 0);
    packW_k<<<2048 * DMOD / 256, 256, 0, s2>>>(W2, W2p, DMOD, DMOD, 0);
    cudaEventRecord(evJoin, s2);

    // main: QKV weight packs into [512][3072], biases, addemb
    packW_k<<<WQW / 256, 256>>>(Wq, Wqp, DMOD, N3, 0);
    packW_k<<<WQW / 256, 256>>>(Wk, Wqp, DMOD, N3, DMOD);
    packW_k<<<WQW / 256, 256>>>(Wv, Wqp, DMOD, N3, 2 * DMOD);
    cudaMemcpyAsync(bqkv,            bq, DMOD * 4, cudaMemcpyDeviceToDevice);
    cudaMemcpyAsync(bqkv + DMOD,     bk, DMOD * 4, cudaMemcpyDeviceToDevice);
    cudaMemcpyAsync(bqkv + 2 * DMOD, bv, DMOD * 4, cudaMemcpyDeviceToDevice);
    addemb_k<<<NTOK, 256>>>(x, in_deg, out_deg, ide, ode, x2);

    // QKV: single fused GEMM N=3072, bias fused, column-split output
    hgemm<<<dim3(N3 / 128, 16, 1), 256, HSMEM_BYTES>>>(
        x2, Wqp, bqkv, qkv, NTOK, N3, DMOD,
        0, 0, ND, 0, 0, 1, DMOD);

    // repack K,V to half2
    packKV_k<<<dim3(HEADS * 64 * NTOK / 256, 1, 2), 256>>>(qkv, Kp, Vp);

    // join: flash needs bias2d (and late packs before Wo gemm)
    cudaStreamWaitEvent(0, evJoin, 0);
    flash_h<<<dim3(1, 32, HEADS), 256, FLASH_SMEM>>>(qkv, Kp, Vp, bias2d, ao);

    // Wo: split-K=2 -> partials; fused reduce+bo+residual(x2)+LN1 -> h1
    hgemm<<<dim3(8, 16, 2), 256, HSMEM_BYTES>>>(
        ao, Wop, nullptr, part, NTOK, DMOD, DMOD, 0, 0, ND, 0, 0, 2, 0);
    red_ln_k<<<NTOK, 256>>>(part, bo, x2, ln1g, ln1b, h1);

    // FFN1 (+b1, relu)
    hgemm<<<dim3(32, 16, 1), 256, HSMEM_BYTES>>>(
        h1, W1p, b1, ff, NTOK, FFD, DMOD, 0, 0, 0, FFD, 1, 1, 0);
    // FFN2: split-K=2 -> partials; fused reduce+b2+residual(h1)+LN2 -> out
    hgemm<<<dim3(8, 16, 2), 256, HSMEM_BYTES>>>(
        ff, W2p, nullptr, part, NTOK, DMOD, FFD, 0, 0, ND, 0, 0, 2, 0);
    red_ln_k<<<NTOK, 256>>>(part, b2, h1, ln2g, ln2b, out);
}